// round 14
// baseline (speedup 1.0000x reference)
#include <cuda_runtime.h>
#include <math.h>
#include <stdint.h>

#define SEQ_C 4096
#define SEQ_Q 128
#define NTOK  4224
#define HID   356
#define HID2  712
#define G4    1424
#define EMB   100
#define QACD  2848

// ---------------- scratch (static device memory) ----------------
constexpr size_t OFF_X    = 0;
constexpr size_t OFF_G    = OFF_X   + (size_t)NTOK*HID;
constexpr size_t OFF_P    = OFF_G   + (size_t)NTOK*HID;
constexpr size_t OFF_XWF  = OFF_P   + (size_t)NTOK*HID;
constexpr size_t OFF_XWB  = OFF_XWF + (size_t)NTOK*G4;
constexpr size_t OFF_CQ   = OFF_XWB + (size_t)NTOK*G4;
constexpr size_t OFF_C2Q  = OFF_CQ  + (size_t)NTOK*HID2;
constexpr size_t OFF_QAC  = OFF_C2Q + (size_t)SEQ_C*HID2;
constexpr size_t OFF_M1   = OFF_QAC + (size_t)SEQ_C*QACD;
constexpr size_t OFF_M2   = OFF_M1  + (size_t)SEQ_C*HID2;
constexpr size_t OFF_ROWM = OFF_M2  + (size_t)SEQ_C*HID2;
constexpr size_t OFF_QD   = OFF_ROWM + SEQ_C;
constexpr size_t OFF_GST  = OFF_QD  + SEQ_Q;
constexpr size_t OFF_Q2C  = OFF_GST + 2;
constexpr size_t OFF_LO   = OFF_Q2C + HID2;
constexpr size_t OFF_ZB   = OFF_LO  + 2*SEQ_C;
constexpr size_t SCR_TOTAL = OFF_ZB + 2*2*G4;

__device__ __align__(16) float g_s[SCR_TOTAL];
__device__ unsigned g_ctr[8];

__device__ __forceinline__ float tanh_fast(float x)
{
    float y;
    asm("tanh.approx.f32 %0, %1;" : "=f"(y) : "f"(x));
    return y;
}

// ---------------- char CNN ----------------
__global__ void cnn_kernel(const int* __restrict__ cc, const int* __restrict__ cq,
                           const float* __restrict__ emb, const float* __restrict__ cw,
                           const float* __restrict__ cb, float* __restrict__ x)
{
    int tok = blockIdx.x;
    const int* ch = (tok < SEQ_C) ? cc + (size_t)tok*16 : cq + (size_t)(tok-SEQ_C)*16;
    __shared__ float xs[16][EMB];
    int t = threadIdx.x;
    for (int i = t; i < 16*EMB; i += 128)
        xs[i/EMB][i%EMB] = emb[(size_t)ch[i/EMB]*EMB + (i%EMB)];
    __syncthreads();
    if (t < EMB) {
        float y[16];
#pragma unroll
        for (int p = 0; p < 16; p++) y[p] = 0.f;
        const float* wb = cw + (size_t)t*EMB*5;
        for (int i = 0; i < EMB; i++) {
            float w0 = wb[i*5+0], w1 = wb[i*5+1], w2 = wb[i*5+2],
                  w3 = wb[i*5+3], w4 = wb[i*5+4];
#pragma unroll
            for (int p = 0; p < 16; p++) {
                float acc = y[p];
                if (p-2 >= 0) acc = fmaf(w0, xs[p-2][i], acc);
                if (p-1 >= 0) acc = fmaf(w1, xs[p-1][i], acc);
                acc = fmaf(w2, xs[p][i], acc);
                if (p+1 < 16) acc = fmaf(w3, xs[p+1][i], acc);
                if (p+2 < 16) acc = fmaf(w4, xs[p+2][i], acc);
                y[p] = acc;
            }
        }
        float m = y[0];
#pragma unroll
        for (int p = 1; p < 16; p++) m = fmaxf(m, y[p]);
        x[(size_t)tok*HID + t] = m + cb[t];
    }
}

__global__ void elmo_copy(const float* __restrict__ ec, const float* __restrict__ eq,
                          float* __restrict__ x)
{
    int idx = blockIdx.x*256 + threadIdx.x;
    if (idx >= NTOK*256) return;
    int tok = idx >> 8, d = idx & 255;
    float v = (tok < SEQ_C) ? ec[(size_t)tok*256 + d] : eq[(size_t)(tok-SEQ_C)*256 + d];
    x[(size_t)tok*HID + EMB + d] = v;
}

// ---------------- SGEMM 64x64 with register prefetch (proven) -----------------
__global__ __launch_bounds__(256) void gemm_abT(
    const float* __restrict__ A, const float* __restrict__ B,
    const float* __restrict__ bias, float* __restrict__ C,
    int M, int N, int K)
{
    __shared__ float As[8][64];
    __shared__ float Bs[8][64];
    int m0 = blockIdx.y*64, n0 = blockIdx.x*64;
    int t = threadIdx.x;
    int tx = t & 15, ty = t >> 4;
    int mm = t >> 2;
    int kk = (t & 3) * 2;
    int gm = m0 + mm, gn = n0 + mm;
    bool mv = gm < M, nv = gn < N;
    const float* Ar = A + (size_t)(mv ? gm : 0)*K;
    const float* Br = B + (size_t)(nv ? gn : 0)*K;
    float2 pa, pb;

    auto ldtile = [&](int k0) {
        int gk = k0 + kk;
        if (gk + 1 < K) {
            pa = mv ? *(const float2*)(Ar + gk) : make_float2(0.f, 0.f);
            pb = nv ? *(const float2*)(Br + gk) : make_float2(0.f, 0.f);
        } else {
            pa.x = (mv && gk < K) ? Ar[gk] : 0.f; pa.y = 0.f;
            pb.x = (nv && gk < K) ? Br[gk] : 0.f; pb.y = 0.f;
        }
    };

    float acc[4][4];
#pragma unroll
    for (int i = 0; i < 4; i++)
#pragma unroll
        for (int j = 0; j < 4; j++) acc[i][j] = 0.f;

    ldtile(0);
    for (int k0 = 0; k0 < K; k0 += 8) {
        As[kk][mm] = pa.x; As[kk+1][mm] = pa.y;
        Bs[kk][mm] = pb.x; Bs[kk+1][mm] = pb.y;
        __syncthreads();
        if (k0 + 8 < K) ldtile(k0 + 8);
#pragma unroll
        for (int q = 0; q < 8; q++) {
            float4 a4 = *(const float4*)&As[q][ty*4];
            float4 b4 = *(const float4*)&Bs[q][tx*4];
            float ar[4] = {a4.x, a4.y, a4.z, a4.w};
            float br[4] = {b4.x, b4.y, b4.z, b4.w};
#pragma unroll
            for (int i = 0; i < 4; i++)
#pragma unroll
                for (int j = 0; j < 4; j++)
                    acc[i][j] = fmaf(ar[i], br[j], acc[i][j]);
        }
        __syncthreads();
    }
#pragma unroll
    for (int i = 0; i < 4; i++) {
        int m = m0 + ty*4 + i;
        if (m >= M) continue;
#pragma unroll
        for (int j = 0; j < 4; j++) {
            int n = n0 + tx*4 + j;
            if (n < N) C[(size_t)m*N + n] = acc[i][j] + bias[n];
        }
    }
}

__global__ void hw_combine(const float* __restrict__ gl, const float* __restrict__ pl,
                           float* __restrict__ x, int n)
{
    int i = blockIdx.x*256 + threadIdx.x;
    if (i >= n) return;
    float g = 1.f/(1.f + __expf(-gl[i]));
    float p = fmaxf(pl[i], 0.f);
    x[i] = g*p + (1.f - g)*x[i];
}

// ---------------- cluster BiLSTM (same-thread store->arrive, cluster release) -
// grid = 32 or 64 CTAs (clusters of 16). cid = bid>>4: seg = cid>>1, dir = cid&1.
// Post-z work all in warp 0: act on t<ndim writes h_new; lanes t<16 each copy
// h_new to rank t's next h buffer and arrive on the SAME thread with
// .release.cluster (orders the remote stores against the peer's acquire-wait).
__global__ __launch_bounds__(384, 1) void lstm_cluster(
    const float* __restrict__ xwf0, const float* __restrict__ xwb0,
    const float* __restrict__ xwf1, const float* __restrict__ xwb1,
    const float* __restrict__ whh,
    const float* __restrict__ h00, const float* __restrict__ h01,
    float* __restrict__ out0, float* __restrict__ out1, int T0, int T1)
{
    __shared__ __align__(16) float h_s[2][360];
    __shared__ float z_loc[96];
    __shared__ __align__(16) float h_new[24];
    __shared__ __align__(8) unsigned long long mbar[2];

    unsigned rank;
    asm("mov.u32 %0, %%cluster_ctarank;" : "=r"(rank));
    int cid = blockIdx.x >> 4;
    int dir = cid & 1;
    int seg = cid >> 1;
    int T = seg ? T1 : T0;
    const float* h0 = seg ? h01 : h00;
    float* out = seg ? out1 : out0;
    const float* xw = dir ? (seg ? xwb1 : xwb0) : (seg ? xwf1 : xwf0);

    int t = threadIdx.x;
    int k = t & 3;
    int r = t >> 2;

    int ndim = (rank < 4u) ? 23 : 22;
    int d0 = (int)rank * 22 + (int)((rank < 4u) ? rank : 4u);
    int nrows = ndim * 4;
    bool valid = r < nrows;
    int rr = valid ? r : (nrows - 1);
    int gate = rr / ndim;
    int dl = rr - gate * ndim;
    int zrow = gate * HID + d0 + dl;

    // pack Whh row slice [k*90 .. k*90+89] as 45 f32x2 pairs
    const float* Wrow = whh + (size_t)dir * G4 * HID + (size_t)zrow * HID;
    uint64_t Wreg[45];
    int col0 = k * 90;
#pragma unroll
    for (int j = 0; j < 45; j++) {
        int c0 = col0 + 2*j;
        float w0 = (c0   < HID) ? Wrow[c0]   : 0.f;
        float w1 = (c0+1 < HID) ? Wrow[c0+1] : 0.f;
        asm("mov.b64 %0, {%1, %2};" : "=l"(Wreg[j]) : "f"(w0), "f"(w1));
    }

    if (t < 360) {
        h_s[0][t] = (t < HID) ? h0[dir*HID + t] : 0.f;
        h_s[1][t] = 0.f;
    }

    uint32_t mb0 = (uint32_t)__cvta_generic_to_shared(&mbar[0]);
    uint32_t mb1 = (uint32_t)__cvta_generic_to_shared(&mbar[1]);
    if (t == 0) {
        asm volatile("mbarrier.init.shared.b64 [%0], %1;" :: "r"(mb0), "r"(16u) : "memory");
        asm volatile("mbarrier.init.shared.b64 [%0], %1;" :: "r"(mb1), "r"(16u) : "memory");
    }

    float c = 0.f;
    if (t < ndim) c = h0[dir*HID + d0 + t];

    float xwv = 0.f;
    if (k == 0 && valid)
        xwv = __ldcg(&xw[(size_t)(dir ? (T-1) : 0) * G4 + zrow]);

    uint32_t hb0 = (uint32_t)__cvta_generic_to_shared(&h_s[0][0]);
    uint32_t hb1 = (uint32_t)__cvta_generic_to_shared(&h_s[1][0]);
    uint32_t hnb = (uint32_t)__cvta_generic_to_shared(&h_new[0]);

    __syncthreads();
    // all CTAs: smem + mbarrier init visible cluster-wide before any peer traffic
    asm volatile("barrier.cluster.arrive.aligned;" ::: "memory");
    asm volatile("barrier.cluster.wait.aligned;" ::: "memory");

    for (int s = 0; s < T; s++) {
        int tt = dir ? (T-1-s) : s;
        int p = s & 1;

        if (s > 0) {
            uint32_t mb = p ? mb1 : mb0;
            unsigned par = (unsigned)(((s - 1) >> 1) & 1);
            unsigned done;
            asm volatile(
                "{\n\t.reg .pred q;\n\t"
                "mbarrier.try_wait.parity.acquire.cluster.shared::cta.b64 q, [%1], %2;\n\t"
                "selp.b32 %0, 1, 0, q;\n\t}"
                : "=r"(done) : "r"(mb), "r"(par) : "memory");
            while (!done) {
                asm volatile(
                    "{\n\t.reg .pred q;\n\t"
                    "mbarrier.try_wait.parity.acquire.cluster.shared::cta.b64 q, [%1], %2, 0x989680;\n\t"
                    "selp.b32 %0, 1, 0, q;\n\t}"
                    : "=r"(done) : "r"(mb), "r"(par) : "memory");
            }
        }

        uint32_t ha = (p ? hb1 : hb0) + (uint32_t)(k*90)*4u;
        uint64_t acc0 = 0ull, acc1 = 0ull;
#pragma unroll
        for (int j = 0; j < 44; j += 2) {
            uint64_t hv0, hv1;
            asm("ld.shared.b64 %0, [%1];" : "=l"(hv0) : "r"(ha + (uint32_t)(j*8)));
            asm("ld.shared.b64 %0, [%1];" : "=l"(hv1) : "r"(ha + (uint32_t)(j*8 + 8)));
            asm("fma.rn.f32x2 %0, %1, %2, %0;" : "+l"(acc0) : "l"(Wreg[j]),   "l"(hv0));
            asm("fma.rn.f32x2 %0, %1, %2, %0;" : "+l"(acc1) : "l"(Wreg[j+1]), "l"(hv1));
        }
        {
            uint64_t hv;
            asm("ld.shared.b64 %0, [%1];" : "=l"(hv) : "r"(ha + (uint32_t)(44*8)));
            asm("fma.rn.f32x2 %0, %1, %2, %0;" : "+l"(acc0) : "l"(Wreg[44]), "l"(hv));
        }
        float lo0, hi0, lo1, hi1;
        asm("mov.b64 {%0, %1}, %2;" : "=f"(lo0), "=f"(hi0) : "l"(acc0));
        asm("mov.b64 {%0, %1}, %2;" : "=f"(lo1), "=f"(hi1) : "l"(acc1));
        float sum = (lo0 + hi0) + (lo1 + hi1);
        sum += __shfl_xor_sync(0xffffffffu, sum, 1);
        sum += __shfl_xor_sync(0xffffffffu, sum, 2);
        if (k == 0 && valid) z_loc[rr] = sum + xwv;
        __syncthreads();

        if (t < 32) {
            if (t < ndim) {
                float zi = z_loc[t];
                float zf = z_loc[ndim + t];
                float zg = z_loc[2*ndim + t];
                float zo = z_loc[3*ndim + t];
                float si = fmaf(0.5f, tanh_fast(0.5f*zi), 0.5f);
                float sf = fmaf(0.5f, tanh_fast(0.5f*zf), 0.5f);
                float so = fmaf(0.5f, tanh_fast(0.5f*zo), 0.5f);
                float tg = tanh_fast(zg);
                c = sf*c + si*tg;
                float h = so * tanh_fast(c);
                h_new[t] = h;
                out[(size_t)tt*HID2 + dir*HID + d0 + t] = h;
            }
            __syncwarp();
            if (t < 16) {
                // copy my CTA's ndim new h values into rank t's next h buffer,
                // then arrive on rank t's mbar from this same thread with
                // cluster-scope release (orders the stores above).
                uint32_t dstb = (p ? hb0 : hb1) + (uint32_t)(d0*4);
                uint32_t ra, rb;
                asm("mapa.shared::cluster.u32 %0, %1, %2;"
                    : "=r"(ra) : "r"(dstb), "r"((unsigned)t));
#pragma unroll
                for (int i = 0; i < 23; i++) {
                    if (i < ndim) {
                        float v;
                        asm volatile("ld.shared.f32 %0, [%1];"
                                     : "=f"(v) : "r"(hnb + (uint32_t)(i*4)));
                        asm volatile("st.shared::cluster.f32 [%0], %1;"
                                     :: "r"(ra + (uint32_t)(i*4)), "f"(v) : "memory");
                    }
                }
                uint32_t mbn = (p ? mb0 : mb1);
                asm("mapa.shared::cluster.u32 %0, %1, %2;"
                    : "=r"(rb) : "r"(mbn), "r"((unsigned)t));
                asm volatile("mbarrier.arrive.release.cluster.shared::cluster.b64 _, [%0];"
                             :: "r"(rb) : "memory");
            }
        }
        if (k == 0 && valid && s+1 < T) {
            int tn = dir ? (T-2-s) : (s+1);
            xwv = __ldcg(&xw[(size_t)tn*G4 + zrow]);
        }
    }
    // no CTA may retire while peers still store into its smem
    asm volatile("barrier.cluster.arrive.aligned;" ::: "memory");
    asm volatile("barrier.cluster.wait.aligned;" ::: "memory");
}

// ---------------- fallback: global-barrier BiLSTM (known-good) ----------------
__global__ __launch_bounds__(384, 1) void lstm_stage(
    const float* __restrict__ xwf, const float* __restrict__ xwb,
    const float* __restrict__ whh, const float* __restrict__ h0,
    float* __restrict__ out, float* __restrict__ zbuf,
    unsigned* __restrict__ ctr, int T)
{
    int dir = blockIdx.x >> 4;
    int base = (blockIdx.x & 15) * 89;
    int t = threadIdx.x;
    int r = t >> 2; if (r > 88) r = 88;
    int k = t & 3;
    __shared__ float h_s[HID];
    const float* W = whh + (size_t)dir*G4*HID + (size_t)(base + r)*HID + k*89;
    float Wreg[89];
#pragma unroll
    for (int j = 0; j < 89; j++) Wreg[j] = W[j];
    float c = 0.f;
    if (t < HID) { float hv = h0[dir*HID + t]; h_s[t] = hv; c = hv; }
    const float* xw = dir ? xwb : xwf;
    int zrow = base + r;
    __syncthreads();
    for (int s = 0; s < T; s++) {
        int tt = dir ? (T-1-s) : s;
        float xwv = __ldcg(&xw[(size_t)tt*G4 + zrow]);
        const float* hp = h_s + k*89;
        float s0 = 0.f, s1 = 0.f;
#pragma unroll
        for (int j = 0; j < 88; j += 2) {
            s0 = fmaf(Wreg[j],   hp[j],   s0);
            s1 = fmaf(Wreg[j+1], hp[j+1], s1);
        }
        s0 = fmaf(Wreg[88], hp[88], s0);
        float sum = s0 + s1;
        sum += __shfl_xor_sync(0xffffffffu, sum, 1);
        sum += __shfl_xor_sync(0xffffffffu, sum, 2);
        float* zb = zbuf + ((size_t)((s & 1)*2 + dir))*G4;
        if (k == 0 && t < HID) __stcg(&zb[zrow], sum + xwv);
        __threadfence();
        __syncthreads();
        if (t == 0) {
            atomicAdd(ctr, 1u);
            unsigned want = 32u*(unsigned)(s+1);
            volatile unsigned* vp = ctr;
            while (*vp < want) { }
        }
        __syncthreads();
        if (t < HID) {
            float zi = __ldcg(&zb[t]);
            float zf = __ldcg(&zb[HID + t]);
            float zg = __ldcg(&zb[2*HID + t]);
            float zo = __ldcg(&zb[3*HID + t]);
            float si = 1.f/(1.f + __expf(-zi));
            float sf = 1.f/(1.f + __expf(-zf));
            float so = 1.f/(1.f + __expf(-zo));
            c = sf*c + si*tanhf(zg);
            float h = so*tanhf(c);
            out[(size_t)tt*HID2 + dir*HID + t] = h;
            h_s[t] = h;
        }
        __syncthreads();
    }
}

// ---------------- attention ----------------
__global__ void qdot_kernel(const float* __restrict__ Q, const float* __restrict__ sw,
                            float* __restrict__ qd)
{
    int q = blockIdx.x, t = threadIdx.x;
    const float* wq = sw + HID2;
    float acc = 0.f;
    for (int d = t; d < HID2; d += 128) acc = fmaf(Q[(size_t)q*HID2 + d], wq[d], acc);
    __shared__ float red[4];
    for (int o = 16; o; o >>= 1) acc += __shfl_xor_sync(~0u, acc, o);
    if ((t & 31) == 0) red[t >> 5] = acc;
    __syncthreads();
    if (t == 0) qd[q] = red[0] + red[1] + red[2] + red[3];
}

__global__ __launch_bounds__(256) void attn_kernel(
    const float* __restrict__ C, const float* __restrict__ Q,
    const float* __restrict__ sw, const float* __restrict__ qd,
    float* __restrict__ c2q, float* __restrict__ rowm)
{
    int c = blockIdx.x, t = threadIdx.x;
    __shared__ float u[HID2];
    __shared__ float sl[SEQ_Q];
    __shared__ float red[8];
    const float* Cr = C + (size_t)c*HID2;
    float cd = 0.f;
    for (int d = t; d < HID2; d += 256) {
        float cv = Cr[d];
        u[d] = cv * sw[2*HID2 + d];
        cd = fmaf(cv, sw[d], cd);
    }
    for (int o = 16; o; o >>= 1) cd += __shfl_xor_sync(~0u, cd, o);
    if ((t & 31) == 0) red[t >> 5] = cd;
    __syncthreads();
    float cdot = red[0]+red[1]+red[2]+red[3]+red[4]+red[5]+red[6]+red[7];
    int qi = t >> 3, lane8 = t & 7;
    for (int qc = 0; qc < 4; qc++) {
        int q = qc*32 + qi;
        const float* Qr = Q + (size_t)q*HID2;
        float acc = 0.f;
        for (int m = 0; m < 89; m++) {
            int d = lane8 + 8*m;
            acc = fmaf(u[d], Qr[d], acc);
        }
        acc += __shfl_xor_sync(~0u, acc, 1);
        acc += __shfl_xor_sync(~0u, acc, 2);
        acc += __shfl_xor_sync(~0u, acc, 4);
        if (lane8 == 0) sl[q] = acc + cdot + qd[q];
    }
    __syncthreads();
    float v = (t < 128) ? sl[t] : -1e30f;
    for (int o = 16; o; o >>= 1) v = fmaxf(v, __shfl_xor_sync(~0u, v, o));
    if ((t & 31) == 0) red[t >> 5] = v;
    __syncthreads();
    float mx = red[0];
#pragma unroll
    for (int i = 1; i < 8; i++) mx = fmaxf(mx, red[i]);
    float e = 0.f;
    if (t < 128) { e = __expf(sl[t] - mx); sl[t] = e; }
    __syncthreads();
    for (int o = 16; o; o >>= 1) e += __shfl_xor_sync(~0u, e, o);
    if ((t & 31) == 0) red[t >> 5] = e;
    __syncthreads();
    float sum = red[0]+red[1]+red[2]+red[3]+red[4]+red[5]+red[6]+red[7];
    float inv = 1.f/sum;
    if (t == 0) rowm[c] = mx;
    for (int d = t; d < HID2; d += 256) {
        float acc = 0.f;
        for (int q = 0; q < SEQ_Q; q++)
            acc = fmaf(sl[q], Q[(size_t)q*HID2 + d], acc);
        c2q[(size_t)c*HID2 + d] = acc * inv;
    }
}

__global__ void q2c_prep(const float* __restrict__ rowm, float* __restrict__ gst,
                         float* __restrict__ q2c)
{
    int t = threadIdx.x;
    __shared__ float red[32];
    __shared__ float sh[2];
    float m = -1e30f;
    for (int i = t; i < SEQ_C; i += 1024) m = fmaxf(m, rowm[i]);
    for (int o = 16; o; o >>= 1) m = fmaxf(m, __shfl_xor_sync(~0u, m, o));
    if ((t & 31) == 0) red[t >> 5] = m;
    __syncthreads();
    if (t < 32) {
        float w = red[t];
        for (int o = 16; o; o >>= 1) w = fmaxf(w, __shfl_xor_sync(~0u, w, o));
        if (t == 0) sh[0] = w;
    }
    __syncthreads();
    float gm = sh[0];
    float e = 0.f;
    for (int i = t; i < SEQ_C; i += 1024) e += __expf(rowm[i] - gm);
    for (int o = 16; o; o >>= 1) e += __shfl_xor_sync(~0u, e, o);
    if ((t & 31) == 0) red[t >> 5] = e;
    __syncthreads();
    if (t < 32) {
        float w = red[t];
        for (int o = 16; o; o >>= 1) w += __shfl_xor_sync(~0u, w, o);
        if (t == 0) { gst[0] = gm; gst[1] = w; }
    }
    if (t < HID2) q2c[t] = 0.f;
}

__global__ void q2c_acc(const float* __restrict__ rowm, const float* __restrict__ gst,
                        const float* __restrict__ C, float* __restrict__ q2c)
{
    int b = blockIdx.x, t = threadIdx.x;
    float gm = gst[0], inv = 1.f/gst[1];
    float a0 = 0.f, a1 = 0.f, a2 = 0.f;
    int d0 = t, d1 = t + 256, d2 = t + 512;
    for (int c = b*128; c < b*128 + 128; c++) {
        float w = __expf(rowm[c] - gm);
        const float* Cr = C + (size_t)c*HID2;
        a0 = fmaf(w, Cr[d0], a0);
        if (d1 < HID2) a1 = fmaf(w, Cr[d1], a1);
        if (d2 < HID2) a2 = fmaf(w, Cr[d2], a2);
    }
    atomicAdd(&q2c[d0], a0*inv);
    if (d1 < HID2) atomicAdd(&q2c[d1], a1*inv);
    if (d2 < HID2) atomicAdd(&q2c[d2], a2*inv);
}

__global__ void qac_kernel(const float* __restrict__ C, const float* __restrict__ c2q,
                           const float* __restrict__ q2c, float* __restrict__ qac)
{
    size_t i = (size_t)blockIdx.x*256 + threadIdx.x;
    if (i >= (size_t)SEQ_C*HID2) return;
    size_t c = i / HID2, d = i % HID2;
    float cv = C[i], aq = c2q[i];
    float* row = qac + c*QACD;
    row[d] = cv;
    row[HID2 + d] = aq;
    row[2*HID2 + d] = cv*aq;
    row[3*HID2 + d] = cv*q2c[d];
}

__global__ void poslogit(const float* __restrict__ qac, const float* __restrict__ M,
                         const float* __restrict__ w, float* __restrict__ lo)
{
    int c = blockIdx.x, t = threadIdx.x;
    float acc = 0.f;
    const float* qr = qac + (size_t)c*QACD;
    for (int j = t; j < QACD; j += 128) acc = fmaf(qr[j], w[j], acc);
    const float* mr = M + (size_t)c*HID2;
    for (int j = t; j < HID2; j += 128) acc = fmaf(mr[j], w[QACD + j], acc);
    __shared__ float red[4];
    for (int o = 16; o; o >>= 1) acc += __shfl_xor_sync(~0u, acc, o);
    if ((t & 31) == 0) red[t >> 5] = acc;
    __syncthreads();
    if (t == 0) lo[c] = red[0] + red[1] + red[2] + red[3];
}

__global__ void final_softmax(const float* __restrict__ lo, float* __restrict__ out)
{
    int t = threadIdx.x;
    __shared__ float red[32];
    __shared__ float sh[2];
    for (int v = 0; v < 2; v++) {
        const float* l = lo + v*SEQ_C;
        float m = -1e30f;
        for (int i = t; i < SEQ_C; i += 1024) m = fmaxf(m, l[i]);
        for (int o = 16; o; o >>= 1) m = fmaxf(m, __shfl_xor_sync(~0u, m, o));
        if ((t & 31) == 0) red[t >> 5] = m;
        __syncthreads();
        if (t < 32) {
            float w = red[t];
            for (int o = 16; o; o >>= 1) w = fmaxf(w, __shfl_xor_sync(~0u, w, o));
            if (t == 0) sh[0] = w;
        }
        __syncthreads();
        float gm = sh[0];
        float e = 0.f;
        for (int i = t; i < SEQ_C; i += 1024) e += __expf(l[i] - gm);
        for (int o = 16; o; o >>= 1) e += __shfl_xor_sync(~0u, e, o);
        if ((t & 31) == 0) red[t >> 5] = e;
        __syncthreads();
        if (t < 32) {
            float w = red[t];
            for (int o = 16; o; o >>= 1) w += __shfl_xor_sync(~0u, w, o);
            if (t == 0) sh[1] = w;
        }
        __syncthreads();
        float inv = 1.f/sh[1];
        for (int i = t; i < SEQ_C; i += 1024) out[v*SEQ_C + i] = __expf(l[i] - gm)*inv;
        __syncthreads();
    }
}

// ---------------- host orchestration ----------------
static inline void gemm(const float* A, const float* B, const float* bias, float* C,
                        int M, int N, int K)
{
    dim3 g((N + 63)/64, (M + 63)/64);
    gemm_abT<<<g, 256>>>(A, B, bias, C, M, N, K);
}

// one launch: seg0 (T0 steps) always; seg1 (T1 steps) iff T1 > 0
static void launch_lstm2(const float* xwf0, const float* xwb0,
                         const float* xwf1, const float* xwb1,
                         const float* whh, const float* h00, const float* h01,
                         float* out0, float* out1, int T0, int T1,
                         float* zb, unsigned* ctr, int ctri)
{
    int nclu = (T1 > 0) ? 4 : 2;
    cudaLaunchConfig_t cfg = {};
    cfg.gridDim = dim3(16*nclu, 1, 1);
    cfg.blockDim = dim3(384, 1, 1);
    cfg.dynamicSmemBytes = 0;
    cfg.stream = 0;
    cudaLaunchAttribute a[1];
    a[0].id = cudaLaunchAttributeClusterDimension;
    a[0].val.clusterDim.x = 16; a[0].val.clusterDim.y = 1; a[0].val.clusterDim.z = 1;
    cfg.attrs = a; cfg.numAttrs = 1;
    cudaError_t e = cudaLaunchKernelEx(&cfg, lstm_cluster, xwf0, xwb0, xwf1, xwb1,
                                       whh, h00, h01, out0, out1, T0, T1);
    if (e != cudaSuccess) {
        (void)cudaGetLastError();
        lstm_stage<<<32, 384>>>(xwf0, xwb0, whh, h00, out0, zb, ctr + ctri, T0);
        if (T1 > 0)
            lstm_stage<<<32, 384>>>(xwf1, xwb1, whh, h01, out1, zb, ctr + ctri + 1, T1);
    }
}

extern "C" void kernel_launch(void* const* d_in, const int* in_sizes, int n_in,
                              void* d_out, int out_size)
{
    (void)in_sizes; (void)n_in; (void)out_size;
    float* S = nullptr; unsigned* CT = nullptr;
    cudaGetSymbolAddress((void**)&S, g_s);
    cudaGetSymbolAddress((void**)&CT, g_ctr);
    cudaFuncSetAttribute(lstm_cluster, cudaFuncAttributeNonPortableClusterSizeAllowed, 1);

    const int*   chars_ctx = (const int*)d_in[0];
    const int*   chars_qry = (const int*)d_in[1];
    const float* elmo_ctx  = (const float*)d_in[2];
    const float* elmo_qry  = (const float*)d_in[3];
    const float* char_emb  = (const float*)d_in[4];
    const float* conv_w    = (const float*)d_in[5];
    const float* conv_b    = (const float*)d_in[6];
    const float* hw_pw     = (const float*)d_in[7];
    const float* hw_pb     = (const float*)d_in[8];
    const float* hw_gw     = (const float*)d_in[9];
    const float* hw_gb     = (const float*)d_in[10];
    const float* ctx_Wih   = (const float*)d_in[11];
    const float* ctx_Whh   = (const float*)d_in[12];
    const float* ctx_b     = (const float*)d_in[13];
    const float* sim_w     = (const float*)d_in[14];
    const float* m1_Wih    = (const float*)d_in[15];
    const float* m1_Whh    = (const float*)d_in[16];
    const float* m1_b      = (const float*)d_in[17];
    const float* m2_Wih    = (const float*)d_in[18];
    const float* m2_Whh    = (const float*)d_in[19];
    const float* m2_b      = (const float*)d_in[20];
    const float* po_Wih    = (const float*)d_in[21];
    const float* po_Whh    = (const float*)d_in[22];
    const float* po_b      = (const float*)d_in[23];
    const float* pos1_w    = (const float*)d_in[24];
    const float* pos2_w    = (const float*)d_in[25];
    const float* h0_ctx_c  = (const float*)d_in[26];
    const float* h0_ctx_q  = (const float*)d_in[27];
    const float* h0_mod    = (const float*)d_in[28];
    const float* h0_pos    = (const float*)d_in[29];

    float* X    = S + OFF_X;
    float* GL   = S + OFF_G;
    float* PL   = S + OFF_P;
    float* XWF  = S + OFF_XWF;
    float* XWB  = S + OFF_XWB;
    float* CQ   = S + OFF_CQ;
    float* C2Q  = S + OFF_C2Q;
    float* QAC  = S + OFF_QAC;
    float* M1   = S + OFF_M1;
    float* M2   = S + OFF_M2;
    float* ROWM = S + OFF_ROWM;
    float* QD   = S + OFF_QD;
    float* GST  = S + OFF_GST;
    float* Q2C  = S + OFF_Q2C;
    float* LO   = S + OFF_LO;
    float* ZB   = S + OFF_ZB;
    float* Cm   = CQ;
    float* Qm   = CQ + (size_t)SEQ_C*HID2;

    cudaMemsetAsync(CT, 0, 8*sizeof(unsigned), 0);

    // embedding
    cnn_kernel<<<NTOK, 128>>>(chars_ctx, chars_qry, char_emb, conv_w, conv_b, X);
    elmo_copy<<<(NTOK*256 + 255)/256, 256>>>(elmo_ctx, elmo_qry, X);

    // highway x2
    for (int l = 0; l < 2; l++) {
        gemm(X, hw_gw + (size_t)l*HID*HID, hw_gb + (size_t)l*HID, GL, NTOK, HID, HID);
        gemm(X, hw_pw + (size_t)l*HID*HID, hw_pb + (size_t)l*HID, PL, NTOK, HID, HID);
        hw_combine<<<(NTOK*HID + 255)/256, 256>>>(GL, PL, X, NTOK*HID);
    }

    // context BiLSTM (C tokens + Q tokens in one 4-cluster launch)
    gemm(X, ctx_Wih,                    ctx_b,      XWF, NTOK, G4, HID);
    gemm(X, ctx_Wih + (size_t)G4*HID,   ctx_b + G4, XWB, NTOK, G4, HID);
    launch_lstm2(XWF, XWB,
                 XWF + (size_t)SEQ_C*G4, XWB + (size_t)SEQ_C*G4,
                 ctx_Whh, h0_ctx_c, h0_ctx_q, Cm, Qm, SEQ_C, SEQ_Q, ZB, CT, 0);

    // attention
    qdot_kernel<<<SEQ_Q, 128>>>(Qm, sim_w, QD);
    attn_kernel<<<SEQ_C, 256>>>(Cm, Qm, sim_w, QD, C2Q, ROWM);
    q2c_prep<<<1, 1024>>>(ROWM, GST, Q2C);
    q2c_acc<<<32, 256>>>(ROWM, GST, Cm, Q2C);
    qac_kernel<<<(int)(((size_t)SEQ_C*HID2 + 255)/256), 256>>>(Cm, C2Q, Q2C, QAC);

    // modeling layer 1
    gemm(QAC, m1_Wih,                    m1_b,      XWF, SEQ_C, G4, QACD);
    gemm(QAC, m1_Wih + (size_t)G4*QACD,  m1_b + G4, XWB, SEQ_C, G4, QACD);
    launch_lstm2(XWF, XWB, XWF, XWB, m1_Whh, h0_mod, h0_mod,
                 M1, M1, SEQ_C, 0, ZB, CT, 2);

    // modeling layer 2
    gemm(M1, m2_Wih,                    m2_b,      XWF, SEQ_C, G4, HID2);
    gemm(M1, m2_Wih + (size_t)G4*HID2,  m2_b + G4, XWB, SEQ_C, G4, HID2);
    launch_lstm2(XWF, XWB, XWF, XWB, m2_Whh, h0_mod + 2*HID, h0_mod + 2*HID,
                 M2, M2, SEQ_C, 0, ZB, CT, 3);

    // pos1 logits
    poslogit<<<SEQ_C, 128>>>(QAC, M2, pos1_w, LO);

    // pos BiLSTM (reuses M1 buffer)
    gemm(M2, po_Wih,                    po_b,      XWF, SEQ_C, G4, HID2);
    gemm(M2, po_Wih + (size_t)G4*HID2,  po_b + G4, XWB, SEQ_C, G4, HID2);
    launch_lstm2(XWF, XWB, XWF, XWB, po_Whh, h0_pos, h0_pos,
                 M1, M1, SEQ_C, 0, ZB, CT, 4);

    // pos2 logits + final softmaxes
    poslogit<<<SEQ_C, 128>>>(QAC, M1, pos2_w, LO + SEQ_C);
    final_softmax<<<1, 1024>>>(LO, (float*)d_out);
}

// round 15
// speedup vs baseline: 1.7752x; 1.7752x over previous
#include <cuda_runtime.h>
#include <math.h>
#include <stdint.h>

#define SEQ_C 4096
#define SEQ_Q 128
#define NTOK  4224
#define HID   356
#define HID2  712
#define G4    1424
#define EMB   100
#define QACD  2848

// ---------------- scratch (static device memory) ----------------
constexpr size_t OFF_X    = 0;
constexpr size_t OFF_G    = OFF_X   + (size_t)NTOK*HID;
constexpr size_t OFF_P    = OFF_G   + (size_t)NTOK*HID;
constexpr size_t OFF_XWF  = OFF_P   + (size_t)NTOK*HID;
constexpr size_t OFF_XWB  = OFF_XWF + (size_t)NTOK*G4;
constexpr size_t OFF_CQ   = OFF_XWB + (size_t)NTOK*G4;
constexpr size_t OFF_C2Q  = OFF_CQ  + (size_t)NTOK*HID2;
constexpr size_t OFF_QAC  = OFF_C2Q + (size_t)SEQ_C*HID2;
constexpr size_t OFF_M1   = OFF_QAC + (size_t)SEQ_C*QACD;
constexpr size_t OFF_M2   = OFF_M1  + (size_t)SEQ_C*HID2;
constexpr size_t OFF_ROWM = OFF_M2  + (size_t)SEQ_C*HID2;
constexpr size_t OFF_QD   = OFF_ROWM + SEQ_C;
constexpr size_t OFF_GST  = OFF_QD  + SEQ_Q;
constexpr size_t OFF_Q2C  = OFF_GST + 2;
constexpr size_t OFF_LO   = OFF_Q2C + HID2;
constexpr size_t OFF_ZB   = OFF_LO  + 2*SEQ_C;
constexpr size_t SCR_TOTAL = OFF_ZB + 2*2*G4;

__device__ __align__(16) float g_s[SCR_TOTAL];
__device__ unsigned g_ctr[8];

__device__ __forceinline__ float tanh_fast(float x)
{
    float y;
    asm("tanh.approx.f32 %0, %1;" : "=f"(y) : "f"(x));
    return y;
}

// ---------------- char CNN ----------------
__global__ void cnn_kernel(const int* __restrict__ cc, const int* __restrict__ cq,
                           const float* __restrict__ emb, const float* __restrict__ cw,
                           const float* __restrict__ cb, float* __restrict__ x)
{
    int tok = blockIdx.x;
    const int* ch = (tok < SEQ_C) ? cc + (size_t)tok*16 : cq + (size_t)(tok-SEQ_C)*16;
    __shared__ float xs[16][EMB];
    int t = threadIdx.x;
    for (int i = t; i < 16*EMB; i += 128)
        xs[i/EMB][i%EMB] = emb[(size_t)ch[i/EMB]*EMB + (i%EMB)];
    __syncthreads();
    if (t < EMB) {
        float y[16];
#pragma unroll
        for (int p = 0; p < 16; p++) y[p] = 0.f;
        const float* wb = cw + (size_t)t*EMB*5;
        for (int i = 0; i < EMB; i++) {
            float w0 = wb[i*5+0], w1 = wb[i*5+1], w2 = wb[i*5+2],
                  w3 = wb[i*5+3], w4 = wb[i*5+4];
#pragma unroll
            for (int p = 0; p < 16; p++) {
                float acc = y[p];
                if (p-2 >= 0) acc = fmaf(w0, xs[p-2][i], acc);
                if (p-1 >= 0) acc = fmaf(w1, xs[p-1][i], acc);
                acc = fmaf(w2, xs[p][i], acc);
                if (p+1 < 16) acc = fmaf(w3, xs[p+1][i], acc);
                if (p+2 < 16) acc = fmaf(w4, xs[p+2][i], acc);
                y[p] = acc;
            }
        }
        float m = y[0];
#pragma unroll
        for (int p = 1; p < 16; p++) m = fmaxf(m, y[p]);
        x[(size_t)tok*HID + t] = m + cb[t];
    }
}

__global__ void elmo_copy(const float* __restrict__ ec, const float* __restrict__ eq,
                          float* __restrict__ x)
{
    int idx = blockIdx.x*256 + threadIdx.x;
    if (idx >= NTOK*256) return;
    int tok = idx >> 8, d = idx & 255;
    float v = (tok < SEQ_C) ? ec[(size_t)tok*256 + d] : eq[(size_t)(tok-SEQ_C)*256 + d];
    x[(size_t)tok*HID + EMB + d] = v;
}

// ---------------- SGEMM 64x64, register prefetch + double-buffered smem -------
__global__ __launch_bounds__(256) void gemm_abT(
    const float* __restrict__ A, const float* __restrict__ B,
    const float* __restrict__ bias, float* __restrict__ C,
    int M, int N, int K)
{
    __shared__ float As[2][8][64];
    __shared__ float Bs[2][8][64];
    int m0 = blockIdx.y*64, n0 = blockIdx.x*64;
    int t = threadIdx.x;
    int tx = t & 15, ty = t >> 4;
    int mm = t >> 2;
    int kk = (t & 3) * 2;
    int gm = m0 + mm, gn = n0 + mm;
    bool mv = gm < M, nv = gn < N;
    const float* Ar = A + (size_t)(mv ? gm : 0)*K;
    const float* Br = B + (size_t)(nv ? gn : 0)*K;
    float2 pa, pb;

    auto ldtile = [&](int k0) {
        int gk = k0 + kk;
        if (gk + 1 < K) {
            pa = mv ? *(const float2*)(Ar + gk) : make_float2(0.f, 0.f);
            pb = nv ? *(const float2*)(Br + gk) : make_float2(0.f, 0.f);
        } else {
            pa.x = (mv && gk < K) ? Ar[gk] : 0.f; pa.y = 0.f;
            pb.x = (nv && gk < K) ? Br[gk] : 0.f; pb.y = 0.f;
        }
    };

    float acc[4][4];
#pragma unroll
    for (int i = 0; i < 4; i++)
#pragma unroll
        for (int j = 0; j < 4; j++) acc[i][j] = 0.f;

    ldtile(0);
    As[0][kk][mm] = pa.x; As[0][kk+1][mm] = pa.y;
    Bs[0][kk][mm] = pb.x; Bs[0][kk+1][mm] = pb.y;
    __syncthreads();
    int cur = 0;
    for (int k0 = 0; k0 < K; k0 += 8) {
        bool more = (k0 + 8 < K);
        if (more) ldtile(k0 + 8);   // prefetch next tile into registers
#pragma unroll
        for (int q = 0; q < 8; q++) {
            float4 a4 = *(const float4*)&As[cur][q][ty*4];
            float4 b4 = *(const float4*)&Bs[cur][q][tx*4];
            float ar[4] = {a4.x, a4.y, a4.z, a4.w};
            float br[4] = {b4.x, b4.y, b4.z, b4.w};
#pragma unroll
            for (int i = 0; i < 4; i++)
#pragma unroll
                for (int j = 0; j < 4; j++)
                    acc[i][j] = fmaf(ar[i], br[j], acc[i][j]);
        }
        if (more) {
            int nxt = cur ^ 1;
            As[nxt][kk][mm] = pa.x; As[nxt][kk+1][mm] = pa.y;
            Bs[nxt][kk][mm] = pb.x; Bs[nxt][kk+1][mm] = pb.y;
            __syncthreads();
            cur = nxt;
        }
    }
#pragma unroll
    for (int i = 0; i < 4; i++) {
        int m = m0 + ty*4 + i;
        if (m >= M) continue;
#pragma unroll
        for (int j = 0; j < 4; j++) {
            int n = n0 + tx*4 + j;
            if (n < N) C[(size_t)m*N + n] = acc[i][j] + bias[n];
        }
    }
}

__global__ void hw_combine(const float* __restrict__ gl, const float* __restrict__ pl,
                           float* __restrict__ x, int n)
{
    int i = blockIdx.x*256 + threadIdx.x;
    if (i >= n) return;
    float g = 1.f/(1.f + __expf(-gl[i]));
    float p = fmaxf(pl[i], 0.f);
    x[i] = g*p + (1.f - g)*x[i];
}

// ---------------- cluster BiLSTM (exact R12 winning body) ---------------------
// grid = 32 or 64 CTAs (clusters of 16). cid = bid>>4: seg = cid>>1, dir = cid&1.
__global__ __launch_bounds__(384, 1) void lstm_cluster(
    const float* __restrict__ xwf0, const float* __restrict__ xwb0,
    const float* __restrict__ xwf1, const float* __restrict__ xwb1,
    const float* __restrict__ whh,
    const float* __restrict__ h00, const float* __restrict__ h01,
    float* __restrict__ out0, float* __restrict__ out1, int T0, int T1)
{
    __shared__ __align__(16) float h_s[2][360];
    __shared__ float z_loc[96];
    __shared__ __align__(8) unsigned long long mbar[2];

    unsigned rank;
    asm("mov.u32 %0, %%cluster_ctarank;" : "=r"(rank));
    int cid = blockIdx.x >> 4;
    int dir = cid & 1;
    int seg = cid >> 1;
    int T = seg ? T1 : T0;
    const float* h0 = seg ? h01 : h00;
    float* out = seg ? out1 : out0;
    const float* xw = dir ? (seg ? xwb1 : xwb0) : (seg ? xwf1 : xwf0);

    int t = threadIdx.x;
    int k = t & 3;
    int r = t >> 2;

    int ndim = (rank < 4u) ? 23 : 22;
    int d0 = (int)rank * 22 + (int)((rank < 4u) ? rank : 4u);
    int nrows = ndim * 4;
    bool valid = r < nrows;
    int rr = valid ? r : (nrows - 1);
    int gate = rr / ndim;
    int dl = rr - gate * ndim;
    int zrow = gate * HID + d0 + dl;

    // pack Whh row slice [k*90 .. k*90+89] as 45 f32x2 pairs
    const float* Wrow = whh + (size_t)dir * G4 * HID + (size_t)zrow * HID;
    uint64_t Wreg[45];
    int col0 = k * 90;
#pragma unroll
    for (int j = 0; j < 45; j++) {
        int c0 = col0 + 2*j;
        float w0 = (c0   < HID) ? Wrow[c0]   : 0.f;
        float w1 = (c0+1 < HID) ? Wrow[c0+1] : 0.f;
        asm("mov.b64 %0, {%1, %2};" : "=l"(Wreg[j]) : "f"(w0), "f"(w1));
    }

    if (t < 360) {
        h_s[0][t] = (t < HID) ? h0[dir*HID + t] : 0.f;
        h_s[1][t] = 0.f;
    }

    uint32_t mb0 = (uint32_t)__cvta_generic_to_shared(&mbar[0]);
    uint32_t mb1 = (uint32_t)__cvta_generic_to_shared(&mbar[1]);
    if (t == 0) {
        asm volatile("mbarrier.init.shared.b64 [%0], %1;" :: "r"(mb0), "r"(16u) : "memory");
        asm volatile("mbarrier.init.shared.b64 [%0], %1;" :: "r"(mb1), "r"(16u) : "memory");
    }

    // activation thread mapping (redundant 4x per dim)
    int adl = t >> 2, ak = t & 3;
    bool act = (t < 4*ndim);
    float c = 0.f;
    if (act) c = h0[dir*HID + d0 + adl];

    float xwv = 0.f;
    if (k == 0 && valid)
        xwv = __ldcg(&xw[(size_t)(dir ? (T-1) : 0) * G4 + zrow]);

    uint32_t hb0 = (uint32_t)__cvta_generic_to_shared(&h_s[0][0]);
    uint32_t hb1 = (uint32_t)__cvta_generic_to_shared(&h_s[1][0]);

    __syncthreads();
    // all CTAs: smem + mbarrier init visible cluster-wide before any peer traffic
    asm volatile("barrier.cluster.arrive.aligned;" ::: "memory");
    asm volatile("barrier.cluster.wait.aligned;" ::: "memory");

    for (int s = 0; s < T; s++) {
        int tt = dir ? (T-1-s) : s;
        int p = s & 1;

        if (s > 0) {
            uint32_t mb = p ? mb1 : mb0;
            unsigned par = (unsigned)(((s - 1) >> 1) & 1);
            unsigned done;
            asm volatile(
                "{\n\t.reg .pred q;\n\t"
                "mbarrier.try_wait.parity.acquire.cluster.shared::cta.b64 q, [%1], %2;\n\t"
                "selp.b32 %0, 1, 0, q;\n\t}"
                : "=r"(done) : "r"(mb), "r"(par) : "memory");
            while (!done) {
                asm volatile(
                    "{\n\t.reg .pred q;\n\t"
                    "mbarrier.try_wait.parity.acquire.cluster.shared::cta.b64 q, [%1], %2, 0x989680;\n\t"
                    "selp.b32 %0, 1, 0, q;\n\t}"
                    : "=r"(done) : "r"(mb), "r"(par) : "memory");
            }
        }

        uint32_t ha = (p ? hb1 : hb0) + (uint32_t)(k*90)*4u;
        uint64_t acc0 = 0ull, acc1 = 0ull;
#pragma unroll
        for (int j = 0; j < 44; j += 2) {
            uint64_t hv0, hv1;
            asm("ld.shared.b64 %0, [%1];" : "=l"(hv0) : "r"(ha + (uint32_t)(j*8)));
            asm("ld.shared.b64 %0, [%1];" : "=l"(hv1) : "r"(ha + (uint32_t)(j*8 + 8)));
            asm("fma.rn.f32x2 %0, %1, %2, %0;" : "+l"(acc0) : "l"(Wreg[j]),   "l"(hv0));
            asm("fma.rn.f32x2 %0, %1, %2, %0;" : "+l"(acc1) : "l"(Wreg[j+1]), "l"(hv1));
        }
        {
            uint64_t hv;
            asm("ld.shared.b64 %0, [%1];" : "=l"(hv) : "r"(ha + (uint32_t)(44*8)));
            asm("fma.rn.f32x2 %0, %1, %2, %0;" : "+l"(acc0) : "l"(Wreg[44]), "l"(hv));
        }
        float lo0, hi0, lo1, hi1;
        asm("mov.b64 {%0, %1}, %2;" : "=f"(lo0), "=f"(hi0) : "l"(acc0));
        asm("mov.b64 {%0, %1}, %2;" : "=f"(lo1), "=f"(hi1) : "l"(acc1));
        float sum = (lo0 + hi0) + (lo1 + hi1);
        sum += __shfl_xor_sync(0xffffffffu, sum, 1);
        sum += __shfl_xor_sync(0xffffffffu, sum, 2);
        if (k == 0 && valid) z_loc[rr] = sum + xwv;
        __syncthreads();

        if (act) {
            float zi = z_loc[adl];
            float zf = z_loc[ndim + adl];
            float zg = z_loc[2*ndim + adl];
            float zo = z_loc[3*ndim + adl];
            float si = fmaf(0.5f, tanh_fast(0.5f*zi), 0.5f);
            float sf = fmaf(0.5f, tanh_fast(0.5f*zf), 0.5f);
            float so = fmaf(0.5f, tanh_fast(0.5f*zo), 0.5f);
            float tg = tanh_fast(zg);
            c = sf*c + si*tg;
            float h = so * tanh_fast(c);
            uint32_t la = (p ? hb0 : hb1) + (uint32_t)(d0 + adl)*4u;  // next buffer
#pragma unroll
            for (int e = 0; e < 4; e++) {
                asm volatile("{.reg .u32 ra; mapa.shared::cluster.u32 ra, %0, %1; "
                             "st.shared::cluster.f32 [ra], %2;}"
                             :: "r"(la), "r"((unsigned)(ak*4 + e)), "f"(h) : "memory");
            }
            if (ak == 0) out[(size_t)tt*HID2 + dir*HID + d0 + adl] = h;
        }
        __syncthreads();   // order all h stores before the arrives below
        if (t < 16) {
            uint32_t mbn = (p ? mb0 : mb1);   // mbar of next buffer
            asm volatile("{.reg .b32 ra; mapa.shared::cluster.u32 ra, %0, %1; "
                         "mbarrier.arrive.shared::cluster.b64 _, [ra];}"
                         :: "r"(mbn), "r"((unsigned)t) : "memory");
        }
        if (k == 0 && valid && s+1 < T) {
            int tn = dir ? (T-2-s) : (s+1);
            xwv = __ldcg(&xw[(size_t)tn*G4 + zrow]);
        }
    }
    // no CTA may retire while peers still store into its smem
    asm volatile("barrier.cluster.arrive.aligned;" ::: "memory");
    asm volatile("barrier.cluster.wait.aligned;" ::: "memory");
}

// ---------------- fallback: global-barrier BiLSTM (known-good) ----------------
__global__ __launch_bounds__(384, 1) void lstm_stage(
    const float* __restrict__ xwf, const float* __restrict__ xwb,
    const float* __restrict__ whh, const float* __restrict__ h0,
    float* __restrict__ out, float* __restrict__ zbuf,
    unsigned* __restrict__ ctr, int T)
{
    int dir = blockIdx.x >> 4;
    int base = (blockIdx.x & 15) * 89;
    int t = threadIdx.x;
    int r = t >> 2; if (r > 88) r = 88;
    int k = t & 3;
    __shared__ float h_s[HID];
    const float* W = whh + (size_t)dir*G4*HID + (size_t)(base + r)*HID + k*89;
    float Wreg[89];
#pragma unroll
    for (int j = 0; j < 89; j++) Wreg[j] = W[j];
    float c = 0.f;
    if (t < HID) { float hv = h0[dir*HID + t]; h_s[t] = hv; c = hv; }
    const float* xw = dir ? xwb : xwf;
    int zrow = base + r;
    __syncthreads();
    for (int s = 0; s < T; s++) {
        int tt = dir ? (T-1-s) : s;
        float xwv = __ldcg(&xw[(size_t)tt*G4 + zrow]);
        const float* hp = h_s + k*89;
        float s0 = 0.f, s1 = 0.f;
#pragma unroll
        for (int j = 0; j < 88; j += 2) {
            s0 = fmaf(Wreg[j],   hp[j],   s0);
            s1 = fmaf(Wreg[j+1], hp[j+1], s1);
        }
        s0 = fmaf(Wreg[88], hp[88], s0);
        float sum = s0 + s1;
        sum += __shfl_xor_sync(0xffffffffu, sum, 1);
        sum += __shfl_xor_sync(0xffffffffu, sum, 2);
        float* zb = zbuf + ((size_t)((s & 1)*2 + dir))*G4;
        if (k == 0 && t < HID) __stcg(&zb[zrow], sum + xwv);
        __threadfence();
        __syncthreads();
        if (t == 0) {
            atomicAdd(ctr, 1u);
            unsigned want = 32u*(unsigned)(s+1);
            volatile unsigned* vp = ctr;
            while (*vp < want) { }
        }
        __syncthreads();
        if (t < HID) {
            float zi = __ldcg(&zb[t]);
            float zf = __ldcg(&zb[HID + t]);
            float zg = __ldcg(&zb[2*HID + t]);
            float zo = __ldcg(&zb[3*HID + t]);
            float si = 1.f/(1.f + __expf(-zi));
            float sf = 1.f/(1.f + __expf(-zf));
            float so = 1.f/(1.f + __expf(-zo));
            c = sf*c + si*tanhf(zg);
            float h = so*tanhf(c);
            out[(size_t)tt*HID2 + dir*HID + t] = h;
            h_s[t] = h;
        }
        __syncthreads();
    }
}

// ---------------- attention ----------------
__global__ void qdot_kernel(const float* __restrict__ Q, const float* __restrict__ sw,
                            float* __restrict__ qd)
{
    int q = blockIdx.x, t = threadIdx.x;
    const float* wq = sw + HID2;
    float acc = 0.f;
    for (int d = t; d < HID2; d += 128) acc = fmaf(Q[(size_t)q*HID2 + d], wq[d], acc);
    __shared__ float red[4];
    for (int o = 16; o; o >>= 1) acc += __shfl_xor_sync(~0u, acc, o);
    if ((t & 31) == 0) red[t >> 5] = acc;
    __syncthreads();
    if (t == 0) qd[q] = red[0] + red[1] + red[2] + red[3];
}

__global__ __launch_bounds__(256) void attn_kernel(
    const float* __restrict__ C, const float* __restrict__ Q,
    const float* __restrict__ sw, const float* __restrict__ qd,
    float* __restrict__ c2q, float* __restrict__ rowm)
{
    int c = blockIdx.x, t = threadIdx.x;
    __shared__ float u[HID2];
    __shared__ float sl[SEQ_Q];
    __shared__ float red[8];
    const float* Cr = C + (size_t)c*HID2;
    float cd = 0.f;
    for (int d = t; d < HID2; d += 256) {
        float cv = Cr[d];
        u[d] = cv * sw[2*HID2 + d];
        cd = fmaf(cv, sw[d], cd);
    }
    for (int o = 16; o; o >>= 1) cd += __shfl_xor_sync(~0u, cd, o);
    if ((t & 31) == 0) red[t >> 5] = cd;
    __syncthreads();
    float cdot = red[0]+red[1]+red[2]+red[3]+red[4]+red[5]+red[6]+red[7];
    int qi = t >> 3, lane8 = t & 7;
    for (int qc = 0; qc < 4; qc++) {
        int q = qc*32 + qi;
        const float* Qr = Q + (size_t)q*HID2;
        float acc = 0.f;
        for (int m = 0; m < 89; m++) {
            int d = lane8 + 8*m;
            acc = fmaf(u[d], Qr[d], acc);
        }
        acc += __shfl_xor_sync(~0u, acc, 1);
        acc += __shfl_xor_sync(~0u, acc, 2);
        acc += __shfl_xor_sync(~0u, acc, 4);
        if (lane8 == 0) sl[q] = acc + cdot + qd[q];
    }
    __syncthreads();
    float v = (t < 128) ? sl[t] : -1e30f;
    for (int o = 16; o; o >>= 1) v = fmaxf(v, __shfl_xor_sync(~0u, v, o));
    if ((t & 31) == 0) red[t >> 5] = v;
    __syncthreads();
    float mx = red[0];
#pragma unroll
    for (int i = 1; i < 8; i++) mx = fmaxf(mx, red[i]);
    float e = 0.f;
    if (t < 128) { e = __expf(sl[t] - mx); sl[t] = e; }
    __syncthreads();
    for (int o = 16; o; o >>= 1) e += __shfl_xor_sync(~0u, e, o);
    if ((t & 31) == 0) red[t >> 5] = e;
    __syncthreads();
    float sum = red[0]+red[1]+red[2]+red[3]+red[4]+red[5]+red[6]+red[7];
    float inv = 1.f/sum;
    if (t == 0) rowm[c] = mx;
    for (int d = t; d < HID2; d += 256) {
        float acc = 0.f;
        for (int q = 0; q < SEQ_Q; q++)
            acc = fmaf(sl[q], Q[(size_t)q*HID2 + d], acc);
        c2q[(size_t)c*HID2 + d] = acc * inv;
    }
}

__global__ void q2c_prep(const float* __restrict__ rowm, float* __restrict__ gst,
                         float* __restrict__ q2c)
{
    int t = threadIdx.x;
    __shared__ float red[32];
    __shared__ float sh[2];
    float m = -1e30f;
    for (int i = t; i < SEQ_C; i += 1024) m = fmaxf(m, rowm[i]);
    for (int o = 16; o; o >>= 1) m = fmaxf(m, __shfl_xor_sync(~0u, m, o));
    if ((t & 31) == 0) red[t >> 5] = m;
    __syncthreads();
    if (t < 32) {
        float w = red[t];
        for (int o = 16; o; o >>= 1) w = fmaxf(w, __shfl_xor_sync(~0u, w, o));
        if (t == 0) sh[0] = w;
    }
    __syncthreads();
    float gm = sh[0];
    float e = 0.f;
    for (int i = t; i < SEQ_C; i += 1024) e += __expf(rowm[i] - gm);
    for (int o = 16; o; o >>= 1) e += __shfl_xor_sync(~0u, e, o);
    if ((t & 31) == 0) red[t >> 5] = e;
    __syncthreads();
    if (t < 32) {
        float w = red[t];
        for (int o = 16; o; o >>= 1) w += __shfl_xor_sync(~0u, w, o);
        if (t == 0) { gst[0] = gm; gst[1] = w; }
    }
    if (t < HID2) q2c[t] = 0.f;
}

__global__ void q2c_acc(const float* __restrict__ rowm, const float* __restrict__ gst,
                        const float* __restrict__ C, float* __restrict__ q2c)
{
    int b = blockIdx.x, t = threadIdx.x;
    float gm = gst[0], inv = 1.f/gst[1];
    float a0 = 0.f, a1 = 0.f, a2 = 0.f;
    int d0 = t, d1 = t + 256, d2 = t + 512;
    for (int c = b*128; c < b*128 + 128; c++) {
        float w = __expf(rowm[c] - gm);
        const float* Cr = C + (size_t)c*HID2;
        a0 = fmaf(w, Cr[d0], a0);
        if (d1 < HID2) a1 = fmaf(w, Cr[d1], a1);
        if (d2 < HID2) a2 = fmaf(w, Cr[d2], a2);
    }
    atomicAdd(&q2c[d0], a0*inv);
    if (d1 < HID2) atomicAdd(&q2c[d1], a1*inv);
    if (d2 < HID2) atomicAdd(&q2c[d2], a2*inv);
}

__global__ void qac_kernel(const float* __restrict__ C, const float* __restrict__ c2q,
                           const float* __restrict__ q2c, float* __restrict__ qac)
{
    size_t i = (size_t)blockIdx.x*256 + threadIdx.x;
    if (i >= (size_t)SEQ_C*HID2) return;
    size_t c = i / HID2, d = i % HID2;
    float cv = C[i], aq = c2q[i];
    float* row = qac + c*QACD;
    row[d] = cv;
    row[HID2 + d] = aq;
    row[2*HID2 + d] = cv*aq;
    row[3*HID2 + d] = cv*q2c[d];
}

__global__ void poslogit(const float* __restrict__ qac, const float* __restrict__ M,
                         const float* __restrict__ w, float* __restrict__ lo)
{
    int c = blockIdx.x, t = threadIdx.x;
    float acc = 0.f;
    const float* qr = qac + (size_t)c*QACD;
    for (int j = t; j < QACD; j += 128) acc = fmaf(qr[j], w[j], acc);
    const float* mr = M + (size_t)c*HID2;
    for (int j = t; j < HID2; j += 128) acc = fmaf(mr[j], w[QACD + j], acc);
    __shared__ float red[4];
    for (int o = 16; o; o >>= 1) acc += __shfl_xor_sync(~0u, acc, o);
    if ((t & 31) == 0) red[t >> 5] = acc;
    __syncthreads();
    if (t == 0) lo[c] = red[0] + red[1] + red[2] + red[3];
}

__global__ void final_softmax(const float* __restrict__ lo, float* __restrict__ out)
{
    int t = threadIdx.x;
    __shared__ float red[32];
    __shared__ float sh[2];
    for (int v = 0; v < 2; v++) {
        const float* l = lo + v*SEQ_C;
        float m = -1e30f;
        for (int i = t; i < SEQ_C; i += 1024) m = fmaxf(m, l[i]);
        for (int o = 16; o; o >>= 1) m = fmaxf(m, __shfl_xor_sync(~0u, m, o));
        if ((t & 31) == 0) red[t >> 5] = m;
        __syncthreads();
        if (t < 32) {
            float w = red[t];
            for (int o = 16; o; o >>= 1) w = fmaxf(w, __shfl_xor_sync(~0u, w, o));
            if (t == 0) sh[0] = w;
        }
        __syncthreads();
        float gm = sh[0];
        float e = 0.f;
        for (int i = t; i < SEQ_C; i += 1024) e += __expf(l[i] - gm);
        for (int o = 16; o; o >>= 1) e += __shfl_xor_sync(~0u, e, o);
        if ((t & 31) == 0) red[t >> 5] = e;
        __syncthreads();
        if (t < 32) {
            float w = red[t];
            for (int o = 16; o; o >>= 1) w += __shfl_xor_sync(~0u, w, o);
            if (t == 0) sh[1] = w;
        }
        __syncthreads();
        float inv = 1.f/sh[1];
        for (int i = t; i < SEQ_C; i += 1024) out[v*SEQ_C + i] = __expf(l[i] - gm)*inv;
        __syncthreads();
    }
}

// ---------------- host orchestration ----------------
static inline void gemm(const float* A, const float* B, const float* bias, float* C,
                        int M, int N, int K)
{
    dim3 g((N + 63)/64, (M + 63)/64);
    gemm_abT<<<g, 256>>>(A, B, bias, C, M, N, K);
}

// one launch: seg0 (T0 steps) always; seg1 (T1 steps) iff T1 > 0
static void launch_lstm2(const float* xwf0, const float* xwb0,
                         const float* xwf1, const float* xwb1,
                         const float* whh, const float* h00, const float* h01,
                         float* out0, float* out1, int T0, int T1,
                         float* zb, unsigned* ctr, int ctri)
{
    int nclu = (T1 > 0) ? 4 : 2;
    cudaLaunchConfig_t cfg = {};
    cfg.gridDim = dim3(16*nclu, 1, 1);
    cfg.blockDim = dim3(384, 1, 1);
    cfg.dynamicSmemBytes = 0;
    cfg.stream = 0;
    cudaLaunchAttribute a[1];
    a[0].id = cudaLaunchAttributeClusterDimension;
    a[0].val.clusterDim.x = 16; a[0].val.clusterDim.y = 1; a[0].val.clusterDim.z = 1;
    cfg.attrs = a; cfg.numAttrs = 1;
    cudaError_t e = cudaLaunchKernelEx(&cfg, lstm_cluster, xwf0, xwb0, xwf1, xwb1,
                                       whh, h00, h01, out0, out1, T0, T1);
    if (e != cudaSuccess) {
        (void)cudaGetLastError();
        lstm_stage<<<32, 384>>>(xwf0, xwb0, whh, h00, out0, zb, ctr + ctri, T0);
        if (T1 > 0)
            lstm_stage<<<32, 384>>>(xwf1, xwb1, whh, h01, out1, zb, ctr + ctri + 1, T1);
    }
}

extern "C" void kernel_launch(void* const* d_in, const int* in_sizes, int n_in,
                              void* d_out, int out_size)
{
    (void)in_sizes; (void)n_in; (void)out_size;
    float* S = nullptr; unsigned* CT = nullptr;
    cudaGetSymbolAddress((void**)&S, g_s);
    cudaGetSymbolAddress((void**)&CT, g_ctr);
    cudaFuncSetAttribute(lstm_cluster, cudaFuncAttributeNonPortableClusterSizeAllowed, 1);

    const int*   chars_ctx = (const int*)d_in[0];
    const int*   chars_qry = (const int*)d_in[1];
    const float* elmo_ctx  = (const float*)d_in[2];
    const float* elmo_qry  = (const float*)d_in[3];
    const float* char_emb  = (const float*)d_in[4];
    const float* conv_w    = (const float*)d_in[5];
    const float* conv_b    = (const float*)d_in[6];
    const float* hw_pw     = (const float*)d_in[7];
    const float* hw_pb     = (const float*)d_in[8];
    const float* hw_gw     = (const float*)d_in[9];
    const float* hw_gb     = (const float*)d_in[10];
    const float* ctx_Wih   = (const float*)d_in[11];
    const float* ctx_Whh   = (const float*)d_in[12];
    const float* ctx_b     = (const float*)d_in[13];
    const float* sim_w     = (const float*)d_in[14];
    const float* m1_Wih    = (const float*)d_in[15];
    const float* m1_Whh    = (const float*)d_in[16];
    const float* m1_b      = (const float*)d_in[17];
    const float* m2_Wih    = (const float*)d_in[18];
    const float* m2_Whh    = (const float*)d_in[19];
    const float* m2_b      = (const float*)d_in[20];
    const float* po_Wih    = (const float*)d_in[21];
    const float* po_Whh    = (const float*)d_in[22];
    const float* po_b      = (const float*)d_in[23];
    const float* pos1_w    = (const float*)d_in[24];
    const float* pos2_w    = (const float*)d_in[25];
    const float* h0_ctx_c  = (const float*)d_in[26];
    const float* h0_ctx_q  = (const float*)d_in[27];
    const float* h0_mod    = (const float*)d_in[28];
    const float* h0_pos    = (const float*)d_in[29];

    float* X    = S + OFF_X;
    float* GL   = S + OFF_G;
    float* PL   = S + OFF_P;
    float* XWF  = S + OFF_XWF;
    float* XWB  = S + OFF_XWB;
    float* CQ   = S + OFF_CQ;
    float* C2Q  = S + OFF_C2Q;
    float* QAC  = S + OFF_QAC;
    float* M1   = S + OFF_M1;
    float* M2   = S + OFF_M2;
    float* ROWM = S + OFF_ROWM;
    float* QD   = S + OFF_QD;
    float* GST  = S + OFF_GST;
    float* Q2C  = S + OFF_Q2C;
    float* LO   = S + OFF_LO;
    float* ZB   = S + OFF_ZB;
    float* Cm   = CQ;
    float* Qm   = CQ + (size_t)SEQ_C*HID2;

    cudaMemsetAsync(CT, 0, 8*sizeof(unsigned), 0);

    // embedding
    cnn_kernel<<<NTOK, 128>>>(chars_ctx, chars_qry, char_emb, conv_w, conv_b, X);
    elmo_copy<<<(NTOK*256 + 255)/256, 256>>>(elmo_ctx, elmo_qry, X);

    // highway x2
    for (int l = 0; l < 2; l++) {
        gemm(X, hw_gw + (size_t)l*HID*HID, hw_gb + (size_t)l*HID, GL, NTOK, HID, HID);
        gemm(X, hw_pw + (size_t)l*HID*HID, hw_pb + (size_t)l*HID, PL, NTOK, HID, HID);
        hw_combine<<<(NTOK*HID + 255)/256, 256>>>(GL, PL, X, NTOK*HID);
    }

    // context BiLSTM (C tokens + Q tokens in one 4-cluster launch)
    gemm(X, ctx_Wih,                    ctx_b,      XWF, NTOK, G4, HID);
    gemm(X, ctx_Wih + (size_t)G4*HID,   ctx_b + G4, XWB, NTOK, G4, HID);
    launch_lstm2(XWF, XWB,
                 XWF + (size_t)SEQ_C*G4, XWB + (size_t)SEQ_C*G4,
                 ctx_Whh, h0_ctx_c, h0_ctx_q, Cm, Qm, SEQ_C, SEQ_Q, ZB, CT, 0);

    // attention
    qdot_kernel<<<SEQ_Q, 128>>>(Qm, sim_w, QD);
    attn_kernel<<<SEQ_C, 256>>>(Cm, Qm, sim_w, QD, C2Q, ROWM);
    q2c_prep<<<1, 1024>>>(ROWM, GST, Q2C);
    q2c_acc<<<32, 256>>>(ROWM, GST, Cm, Q2C);
    qac_kernel<<<(int)(((size_t)SEQ_C*HID2 + 255)/256), 256>>>(Cm, C2Q, Q2C, QAC);

    // modeling layer 1
    gemm(QAC, m1_Wih,                    m1_b,      XWF, SEQ_C, G4, QACD);
    gemm(QAC, m1_Wih + (size_t)G4*QACD,  m1_b + G4, XWB, SEQ_C, G4, QACD);
    launch_lstm2(XWF, XWB, XWF, XWB, m1_Whh, h0_mod, h0_mod,
                 M1, M1, SEQ_C, 0, ZB, CT, 2);

    // modeling layer 2
    gemm(M1, m2_Wih,                    m2_b,      XWF, SEQ_C, G4, HID2);
    gemm(M1, m2_Wih + (size_t)G4*HID2,  m2_b + G4, XWB, SEQ_C, G4, HID2);
    launch_lstm2(XWF, XWB, XWF, XWB, m2_Whh, h0_mod + 2*HID, h0_mod + 2*HID,
                 M2, M2, SEQ_C, 0, ZB, CT, 3);

    // pos1 logits
    poslogit<<<SEQ_C, 128>>>(QAC, M2, pos1_w, LO);

    // pos BiLSTM (reuses M1 buffer)
    gemm(M2, po_Wih,                    po_b,      XWF, SEQ_C, G4, HID2);
    gemm(M2, po_Wih + (size_t)G4*HID2,  po_b + G4, XWB, SEQ_C, G4, HID2);
    launch_lstm2(XWF, XWB, XWF, XWB, po_Whh, h0_pos, h0_pos,
                 M1, M1, SEQ_C, 0, ZB, CT, 4);

    // pos2 logits + final softmaxes
    poslogit<<<SEQ_C, 128>>>(QAC, M1, pos2_w, LO + SEQ_C);
    final_softmax<<<1, 1024>>>(LO, (float*)d_out);
}

// round 16
// speedup vs baseline: 1.8033x; 1.0158x over previous
#include <cuda_runtime.h>
#include <math.h>
#include <stdint.h>

#define SEQ_C 4096
#define SEQ_Q 128
#define NTOK  4224
#define HID   356
#define HID2  712
#define G4    1424
#define EMB   100
#define QACD  2848

// ---------------- scratch (static device memory) ----------------
constexpr size_t OFF_X    = 0;
constexpr size_t OFF_G    = OFF_X   + (size_t)NTOK*HID;
constexpr size_t OFF_P    = OFF_G   + (size_t)NTOK*HID;
constexpr size_t OFF_XWF  = OFF_P   + (size_t)NTOK*HID;
constexpr size_t OFF_XWB  = OFF_XWF + (size_t)NTOK*G4;
constexpr size_t OFF_CQ   = OFF_XWB + (size_t)NTOK*G4;
constexpr size_t OFF_C2Q  = OFF_CQ  + (size_t)NTOK*HID2;
constexpr size_t OFF_QAC  = OFF_C2Q + (size_t)SEQ_C*HID2;
constexpr size_t OFF_M1   = OFF_QAC + (size_t)SEQ_C*QACD;
constexpr size_t OFF_M2   = OFF_M1  + (size_t)SEQ_C*HID2;
constexpr size_t OFF_ROWM = OFF_M2  + (size_t)SEQ_C*HID2;
constexpr size_t OFF_QD   = OFF_ROWM + SEQ_C;
constexpr size_t OFF_GST  = OFF_QD  + SEQ_Q;
constexpr size_t OFF_Q2C  = OFF_GST + 2;
constexpr size_t OFF_LO   = OFF_Q2C + HID2;
constexpr size_t OFF_ZB   = OFF_LO  + 2*SEQ_C;
constexpr size_t SCR_TOTAL = OFF_ZB + 2*2*G4;

__device__ __align__(16) float g_s[SCR_TOTAL];
__device__ unsigned g_ctr[8];

__device__ __forceinline__ float tanh_fast(float x)
{
    float y;
    asm("tanh.approx.f32 %0, %1;" : "=f"(y) : "f"(x));
    return y;
}

// ---------------- char CNN ----------------
__global__ void cnn_kernel(const int* __restrict__ cc, const int* __restrict__ cq,
                           const float* __restrict__ emb, const float* __restrict__ cw,
                           const float* __restrict__ cb, float* __restrict__ x)
{
    int tok = blockIdx.x;
    const int* ch = (tok < SEQ_C) ? cc + (size_t)tok*16 : cq + (size_t)(tok-SEQ_C)*16;
    __shared__ float xs[16][EMB];
    int t = threadIdx.x;
    for (int i = t; i < 16*EMB; i += 128)
        xs[i/EMB][i%EMB] = emb[(size_t)ch[i/EMB]*EMB + (i%EMB)];
    __syncthreads();
    if (t < EMB) {
        float y[16];
#pragma unroll
        for (int p = 0; p < 16; p++) y[p] = 0.f;
        const float* wb = cw + (size_t)t*EMB*5;
        for (int i = 0; i < EMB; i++) {
            float w0 = wb[i*5+0], w1 = wb[i*5+1], w2 = wb[i*5+2],
                  w3 = wb[i*5+3], w4 = wb[i*5+4];
#pragma unroll
            for (int p = 0; p < 16; p++) {
                float acc = y[p];
                if (p-2 >= 0) acc = fmaf(w0, xs[p-2][i], acc);
                if (p-1 >= 0) acc = fmaf(w1, xs[p-1][i], acc);
                acc = fmaf(w2, xs[p][i], acc);
                if (p+1 < 16) acc = fmaf(w3, xs[p+1][i], acc);
                if (p+2 < 16) acc = fmaf(w4, xs[p+2][i], acc);
                y[p] = acc;
            }
        }
        float m = y[0];
#pragma unroll
        for (int p = 1; p < 16; p++) m = fmaxf(m, y[p]);
        x[(size_t)tok*HID + t] = m + cb[t];
    }
}

__global__ void elmo_copy(const float* __restrict__ ec, const float* __restrict__ eq,
                          float* __restrict__ x)
{
    int idx = blockIdx.x*256 + threadIdx.x;
    if (idx >= NTOK*256) return;
    int tok = idx >> 8, d = idx & 255;
    float v = (tok < SEQ_C) ? ec[(size_t)tok*256 + d] : eq[(size_t)(tok-SEQ_C)*256 + d];
    x[(size_t)tok*HID + EMB + d] = v;
}

// ---------------- SGEMM 64x64, BK=16, register prefetch ----------------------
__global__ __launch_bounds__(256) void gemm_abT(
    const float* __restrict__ A, const float* __restrict__ B,
    const float* __restrict__ bias, float* __restrict__ C,
    int M, int N, int K)
{
    __shared__ float As[16][64];
    __shared__ float Bs[16][64];
    int m0 = blockIdx.y*64, n0 = blockIdx.x*64;
    int t = threadIdx.x;
    int tx = t & 15, ty = t >> 4;
    int mm = t >> 2;          // 0..63
    int kk = (t & 3) * 4;     // 0,4,8,12
    int gm = m0 + mm, gn = n0 + mm;
    bool mv = gm < M, nv = gn < N;
    const float* Ar = A + (size_t)(mv ? gm : 0)*K;
    const float* Br = B + (size_t)(nv ? gn : 0)*K;
    float4 pa, pb;

    auto ldtile = [&](int k0) {
        int gk = k0 + kk;
        if (gk + 3 < K) {       // K%4==0 for all call sites; rows 16B-aligned
            pa = mv ? *(const float4*)(Ar + gk) : make_float4(0.f,0.f,0.f,0.f);
            pb = nv ? *(const float4*)(Br + gk) : make_float4(0.f,0.f,0.f,0.f);
        } else {
            pa.x = (mv && gk   < K) ? Ar[gk]   : 0.f;
            pa.y = (mv && gk+1 < K) ? Ar[gk+1] : 0.f;
            pa.z = (mv && gk+2 < K) ? Ar[gk+2] : 0.f;
            pa.w = (mv && gk+3 < K) ? Ar[gk+3] : 0.f;
            pb.x = (nv && gk   < K) ? Br[gk]   : 0.f;
            pb.y = (nv && gk+1 < K) ? Br[gk+1] : 0.f;
            pb.z = (nv && gk+2 < K) ? Br[gk+2] : 0.f;
            pb.w = (nv && gk+3 < K) ? Br[gk+3] : 0.f;
        }
    };

    float acc[4][4];
#pragma unroll
    for (int i = 0; i < 4; i++)
#pragma unroll
        for (int j = 0; j < 4; j++) acc[i][j] = 0.f;

    ldtile(0);
    for (int k0 = 0; k0 < K; k0 += 16) {
        As[kk][mm] = pa.x; As[kk+1][mm] = pa.y; As[kk+2][mm] = pa.z; As[kk+3][mm] = pa.w;
        Bs[kk][mm] = pb.x; Bs[kk+1][mm] = pb.y; Bs[kk+2][mm] = pb.z; Bs[kk+3][mm] = pb.w;
        __syncthreads();
        if (k0 + 16 < K) ldtile(k0 + 16);   // prefetch next tile while computing
#pragma unroll
        for (int q = 0; q < 16; q++) {
            float4 a4 = *(const float4*)&As[q][ty*4];
            float4 b4 = *(const float4*)&Bs[q][tx*4];
            float ar[4] = {a4.x, a4.y, a4.z, a4.w};
            float br[4] = {b4.x, b4.y, b4.z, b4.w};
#pragma unroll
            for (int i = 0; i < 4; i++)
#pragma unroll
                for (int j = 0; j < 4; j++)
                    acc[i][j] = fmaf(ar[i], br[j], acc[i][j]);
        }
        __syncthreads();
    }
#pragma unroll
    for (int i = 0; i < 4; i++) {
        int m = m0 + ty*4 + i;
        if (m >= M) continue;
#pragma unroll
        for (int j = 0; j < 4; j++) {
            int n = n0 + tx*4 + j;
            if (n < N) C[(size_t)m*N + n] = acc[i][j] + bias[n];
        }
    }
}

__global__ void hw_combine(const float* __restrict__ gl, const float* __restrict__ pl,
                           float* __restrict__ x, int n)
{
    int i = blockIdx.x*256 + threadIdx.x;
    if (i >= n) return;
    float g = 1.f/(1.f + __expf(-gl[i]));
    float p = fmaxf(pl[i], 0.f);
    x[i] = g*p + (1.f - g)*x[i];
}

// ---------------- cluster BiLSTM (exact R12 winning body) ---------------------
// grid = 32 or 64 CTAs (clusters of 16). cid = bid>>4: seg = cid>>1, dir = cid&1.
__global__ __launch_bounds__(384, 1) void lstm_cluster(
    const float* __restrict__ xwf0, const float* __restrict__ xwb0,
    const float* __restrict__ xwf1, const float* __restrict__ xwb1,
    const float* __restrict__ whh,
    const float* __restrict__ h00, const float* __restrict__ h01,
    float* __restrict__ out0, float* __restrict__ out1, int T0, int T1)
{
    __shared__ __align__(16) float h_s[2][360];
    __shared__ float z_loc[96];
    __shared__ __align__(8) unsigned long long mbar[2];

    unsigned rank;
    asm("mov.u32 %0, %%cluster_ctarank;" : "=r"(rank));
    int cid = blockIdx.x >> 4;
    int dir = cid & 1;
    int seg = cid >> 1;
    int T = seg ? T1 : T0;
    const float* h0 = seg ? h01 : h00;
    float* out = seg ? out1 : out0;
    const float* xw = dir ? (seg ? xwb1 : xwb0) : (seg ? xwf1 : xwf0);

    int t = threadIdx.x;
    int k = t & 3;
    int r = t >> 2;

    int ndim = (rank < 4u) ? 23 : 22;
    int d0 = (int)rank * 22 + (int)((rank < 4u) ? rank : 4u);
    int nrows = ndim * 4;
    bool valid = r < nrows;
    int rr = valid ? r : (nrows - 1);
    int gate = rr / ndim;
    int dl = rr - gate * ndim;
    int zrow = gate * HID + d0 + dl;

    // pack Whh row slice [k*90 .. k*90+89] as 45 f32x2 pairs
    const float* Wrow = whh + (size_t)dir * G4 * HID + (size_t)zrow * HID;
    uint64_t Wreg[45];
    int col0 = k * 90;
#pragma unroll
    for (int j = 0; j < 45; j++) {
        int c0 = col0 + 2*j;
        float w0 = (c0   < HID) ? Wrow[c0]   : 0.f;
        float w1 = (c0+1 < HID) ? Wrow[c0+1] : 0.f;
        asm("mov.b64 %0, {%1, %2};" : "=l"(Wreg[j]) : "f"(w0), "f"(w1));
    }

    if (t < 360) {
        h_s[0][t] = (t < HID) ? h0[dir*HID + t] : 0.f;
        h_s[1][t] = 0.f;
    }

    uint32_t mb0 = (uint32_t)__cvta_generic_to_shared(&mbar[0]);
    uint32_t mb1 = (uint32_t)__cvta_generic_to_shared(&mbar[1]);
    if (t == 0) {
        asm volatile("mbarrier.init.shared.b64 [%0], %1;" :: "r"(mb0), "r"(16u) : "memory");
        asm volatile("mbarrier.init.shared.b64 [%0], %1;" :: "r"(mb1), "r"(16u) : "memory");
    }

    // activation thread mapping (redundant 4x per dim)
    int adl = t >> 2, ak = t & 3;
    bool act = (t < 4*ndim);
    float c = 0.f;
    if (act) c = h0[dir*HID + d0 + adl];

    float xwv = 0.f;
    if (k == 0 && valid)
        xwv = __ldcg(&xw[(size_t)(dir ? (T-1) : 0) * G4 + zrow]);

    uint32_t hb0 = (uint32_t)__cvta_generic_to_shared(&h_s[0][0]);
    uint32_t hb1 = (uint32_t)__cvta_generic_to_shared(&h_s[1][0]);

    __syncthreads();
    // all CTAs: smem + mbarrier init visible cluster-wide before any peer traffic
    asm volatile("barrier.cluster.arrive.aligned;" ::: "memory");
    asm volatile("barrier.cluster.wait.aligned;" ::: "memory");

    for (int s = 0; s < T; s++) {
        int tt = dir ? (T-1-s) : s;
        int p = s & 1;

        if (s > 0) {
            uint32_t mb = p ? mb1 : mb0;
            unsigned par = (unsigned)(((s - 1) >> 1) & 1);
            unsigned done;
            asm volatile(
                "{\n\t.reg .pred q;\n\t"
                "mbarrier.try_wait.parity.acquire.cluster.shared::cta.b64 q, [%1], %2;\n\t"
                "selp.b32 %0, 1, 0, q;\n\t}"
                : "=r"(done) : "r"(mb), "r"(par) : "memory");
            while (!done) {
                asm volatile(
                    "{\n\t.reg .pred q;\n\t"
                    "mbarrier.try_wait.parity.acquire.cluster.shared::cta.b64 q, [%1], %2, 0x989680;\n\t"
                    "selp.b32 %0, 1, 0, q;\n\t}"
                    : "=r"(done) : "r"(mb), "r"(par) : "memory");
            }
        }

        uint32_t ha = (p ? hb1 : hb0) + (uint32_t)(k*90)*4u;
        uint64_t acc0 = 0ull, acc1 = 0ull;
#pragma unroll
        for (int j = 0; j < 44; j += 2) {
            uint64_t hv0, hv1;
            asm("ld.shared.b64 %0, [%1];" : "=l"(hv0) : "r"(ha + (uint32_t)(j*8)));
            asm("ld.shared.b64 %0, [%1];" : "=l"(hv1) : "r"(ha + (uint32_t)(j*8 + 8)));
            asm("fma.rn.f32x2 %0, %1, %2, %0;" : "+l"(acc0) : "l"(Wreg[j]),   "l"(hv0));
            asm("fma.rn.f32x2 %0, %1, %2, %0;" : "+l"(acc1) : "l"(Wreg[j+1]), "l"(hv1));
        }
        {
            uint64_t hv;
            asm("ld.shared.b64 %0, [%1];" : "=l"(hv) : "r"(ha + (uint32_t)(44*8)));
            asm("fma.rn.f32x2 %0, %1, %2, %0;" : "+l"(acc0) : "l"(Wreg[44]), "l"(hv));
        }
        float lo0, hi0, lo1, hi1;
        asm("mov.b64 {%0, %1}, %2;" : "=f"(lo0), "=f"(hi0) : "l"(acc0));
        asm("mov.b64 {%0, %1}, %2;" : "=f"(lo1), "=f"(hi1) : "l"(acc1));
        float sum = (lo0 + hi0) + (lo1 + hi1);
        sum += __shfl_xor_sync(0xffffffffu, sum, 1);
        sum += __shfl_xor_sync(0xffffffffu, sum, 2);
        if (k == 0 && valid) z_loc[rr] = sum + xwv;
        __syncthreads();

        if (act) {
            float zi = z_loc[adl];
            float zf = z_loc[ndim + adl];
            float zg = z_loc[2*ndim + adl];
            float zo = z_loc[3*ndim + adl];
            float si = fmaf(0.5f, tanh_fast(0.5f*zi), 0.5f);
            float sf = fmaf(0.5f, tanh_fast(0.5f*zf), 0.5f);
            float so = fmaf(0.5f, tanh_fast(0.5f*zo), 0.5f);
            float tg = tanh_fast(zg);
            c = sf*c + si*tg;
            float h = so * tanh_fast(c);
            uint32_t la = (p ? hb0 : hb1) + (uint32_t)(d0 + adl)*4u;  // next buffer
#pragma unroll
            for (int e = 0; e < 4; e++) {
                asm volatile("{.reg .u32 ra; mapa.shared::cluster.u32 ra, %0, %1; "
                             "st.shared::cluster.f32 [ra], %2;}"
                             :: "r"(la), "r"((unsigned)(ak*4 + e)), "f"(h) : "memory");
            }
            if (ak == 0) out[(size_t)tt*HID2 + dir*HID + d0 + adl] = h;
        }
        __syncthreads();   // order all h stores before the arrives below
        if (t < 16) {
            uint32_t mbn = (p ? mb0 : mb1);   // mbar of next buffer
            asm volatile("{.reg .b32 ra; mapa.shared::cluster.u32 ra, %0, %1; "
                         "mbarrier.arrive.shared::cluster.b64 _, [ra];}"
                         :: "r"(mbn), "r"((unsigned)t) : "memory");
        }
        if (k == 0 && valid && s+1 < T) {
            int tn = dir ? (T-2-s) : (s+1);
            xwv = __ldcg(&xw[(size_t)tn*G4 + zrow]);
        }
    }
    // no CTA may retire while peers still store into its smem
    asm volatile("barrier.cluster.arrive.aligned;" ::: "memory");
    asm volatile("barrier.cluster.wait.aligned;" ::: "memory");
}

// ---------------- fallback: global-barrier BiLSTM (known-good) ----------------
__global__ __launch_bounds__(384, 1) void lstm_stage(
    const float* __restrict__ xwf, const float* __restrict__ xwb,
    const float* __restrict__ whh, const float* __restrict__ h0,
    float* __restrict__ out, float* __restrict__ zbuf,
    unsigned* __restrict__ ctr, int T)
{
    int dir = blockIdx.x >> 4;
    int base = (blockIdx.x & 15) * 89;
    int t = threadIdx.x;
    int r = t >> 2; if (r > 88) r = 88;
    int k = t & 3;
    __shared__ float h_s[HID];
    const float* W = whh + (size_t)dir*G4*HID + (size_t)(base + r)*HID + k*89;
    float Wreg[89];
#pragma unroll
    for (int j = 0; j < 89; j++) Wreg[j] = W[j];
    float c = 0.f;
    if (t < HID) { float hv = h0[dir*HID + t]; h_s[t] = hv; c = hv; }
    const float* xw = dir ? xwb : xwf;
    int zrow = base + r;
    __syncthreads();
    for (int s = 0; s < T; s++) {
        int tt = dir ? (T-1-s) : s;
        float xwv = __ldcg(&xw[(size_t)tt*G4 + zrow]);
        const float* hp = h_s + k*89;
        float s0 = 0.f, s1 = 0.f;
#pragma unroll
        for (int j = 0; j < 88; j += 2) {
            s0 = fmaf(Wreg[j],   hp[j],   s0);
            s1 = fmaf(Wreg[j+1], hp[j+1], s1);
        }
        s0 = fmaf(Wreg[88], hp[88], s0);
        float sum = s0 + s1;
        sum += __shfl_xor_sync(0xffffffffu, sum, 1);
        sum += __shfl_xor_sync(0xffffffffu, sum, 2);
        float* zb = zbuf + ((size_t)((s & 1)*2 + dir))*G4;
        if (k == 0 && t < HID) __stcg(&zb[zrow], sum + xwv);
        __threadfence();
        __syncthreads();
        if (t == 0) {
            atomicAdd(ctr, 1u);
            unsigned want = 32u*(unsigned)(s+1);
            volatile unsigned* vp = ctr;
            while (*vp < want) { }
        }
        __syncthreads();
        if (t < HID) {
            float zi = __ldcg(&zb[t]);
            float zf = __ldcg(&zb[HID + t]);
            float zg = __ldcg(&zb[2*HID + t]);
            float zo = __ldcg(&zb[3*HID + t]);
            float si = 1.f/(1.f + __expf(-zi));
            float sf = 1.f/(1.f + __expf(-zf));
            float so = 1.f/(1.f + __expf(-zo));
            c = sf*c + si*tanhf(zg);
            float h = so*tanhf(c);
            out[(size_t)tt*HID2 + dir*HID + t] = h;
            h_s[t] = h;
        }
        __syncthreads();
    }
}

// ---------------- attention ----------------
__global__ void qdot_kernel(const float* __restrict__ Q, const float* __restrict__ sw,
                            float* __restrict__ qd)
{
    int q = blockIdx.x, t = threadIdx.x;
    const float* wq = sw + HID2;
    float acc = 0.f;
    for (int d = t; d < HID2; d += 128) acc = fmaf(Q[(size_t)q*HID2 + d], wq[d], acc);
    __shared__ float red[4];
    for (int o = 16; o; o >>= 1) acc += __shfl_xor_sync(~0u, acc, o);
    if ((t & 31) == 0) red[t >> 5] = acc;
    __syncthreads();
    if (t == 0) qd[q] = red[0] + red[1] + red[2] + red[3];
}

__global__ __launch_bounds__(256) void attn_kernel(
    const float* __restrict__ C, const float* __restrict__ Q,
    const float* __restrict__ sw, const float* __restrict__ qd,
    float* __restrict__ c2q, float* __restrict__ rowm)
{
    int c = blockIdx.x, t = threadIdx.x;
    __shared__ float u[HID2];
    __shared__ float sl[SEQ_Q];
    __shared__ float red[8];
    const float* Cr = C + (size_t)c*HID2;
    float cd = 0.f;
    for (int d = t; d < HID2; d += 256) {
        float cv = Cr[d];
        u[d] = cv * sw[2*HID2 + d];
        cd = fmaf(cv, sw[d], cd);
    }
    for (int o = 16; o; o >>= 1) cd += __shfl_xor_sync(~0u, cd, o);
    if ((t & 31) == 0) red[t >> 5] = cd;
    __syncthreads();
    float cdot = red[0]+red[1]+red[2]+red[3]+red[4]+red[5]+red[6]+red[7];
    int qi = t >> 3, lane8 = t & 7;
    for (int qc = 0; qc < 4; qc++) {
        int q = qc*32 + qi;
        const float* Qr = Q + (size_t)q*HID2;
        float acc = 0.f;
        for (int m = 0; m < 89; m++) {
            int d = lane8 + 8*m;
            acc = fmaf(u[d], Qr[d], acc);
        }
        acc += __shfl_xor_sync(~0u, acc, 1);
        acc += __shfl_xor_sync(~0u, acc, 2);
        acc += __shfl_xor_sync(~0u, acc, 4);
        if (lane8 == 0) sl[q] = acc + cdot + qd[q];
    }
    __syncthreads();
    float v = (t < 128) ? sl[t] : -1e30f;
    for (int o = 16; o; o >>= 1) v = fmaxf(v, __shfl_xor_sync(~0u, v, o));
    if ((t & 31) == 0) red[t >> 5] = v;
    __syncthreads();
    float mx = red[0];
#pragma unroll
    for (int i = 1; i < 8; i++) mx = fmaxf(mx, red[i]);
    float e = 0.f;
    if (t < 128) { e = __expf(sl[t] - mx); sl[t] = e; }
    __syncthreads();
    for (int o = 16; o; o >>= 1) e += __shfl_xor_sync(~0u, e, o);
    if ((t & 31) == 0) red[t >> 5] = e;
    __syncthreads();
    float sum = red[0]+red[1]+red[2]+red[3]+red[4]+red[5]+red[6]+red[7];
    float inv = 1.f/sum;
    if (t == 0) rowm[c] = mx;
    for (int d = t; d < HID2; d += 256) {
        float acc = 0.f;
        for (int q = 0; q < SEQ_Q; q++)
            acc = fmaf(sl[q], Q[(size_t)q*HID2 + d], acc);
        c2q[(size_t)c*HID2 + d] = acc * inv;
    }
}

__global__ void q2c_prep(const float* __restrict__ rowm, float* __restrict__ gst,
                         float* __restrict__ q2c)
{
    int t = threadIdx.x;
    __shared__ float red[32];
    __shared__ float sh[2];
    float m = -1e30f;
    for (int i = t; i < SEQ_C; i += 1024) m = fmaxf(m, rowm[i]);
    for (int o = 16; o; o >>= 1) m = fmaxf(m, __shfl_xor_sync(~0u, m, o));
    if ((t & 31) == 0) red[t >> 5] = m;
    __syncthreads();
    if (t < 32) {
        float w = red[t];
        for (int o = 16; o; o >>= 1) w = fmaxf(w, __shfl_xor_sync(~0u, w, o));
        if (t == 0) sh[0] = w;
    }
    __syncthreads();
    float gm = sh[0];
    float e = 0.f;
    for (int i = t; i < SEQ_C; i += 1024) e += __expf(rowm[i] - gm);
    for (int o = 16; o; o >>= 1) e += __shfl_xor_sync(~0u, e, o);
    if ((t & 31) == 0) red[t >> 5] = e;
    __syncthreads();
    if (t < 32) {
        float w = red[t];
        for (int o = 16; o; o >>= 1) w += __shfl_xor_sync(~0u, w, o);
        if (t == 0) { gst[0] = gm; gst[1] = w; }
    }
    if (t < HID2) q2c[t] = 0.f;
}

__global__ void q2c_acc(const float* __restrict__ rowm, const float* __restrict__ gst,
                        const float* __restrict__ C, float* __restrict__ q2c)
{
    int b = blockIdx.x, t = threadIdx.x;
    float gm = gst[0], inv = 1.f/gst[1];
    float a0 = 0.f, a1 = 0.f, a2 = 0.f;
    int d0 = t, d1 = t + 256, d2 = t + 512;
    for (int c = b*128; c < b*128 + 128; c++) {
        float w = __expf(rowm[c] - gm);
        const float* Cr = C + (size_t)c*HID2;
        a0 = fmaf(w, Cr[d0], a0);
        if (d1 < HID2) a1 = fmaf(w, Cr[d1], a1);
        if (d2 < HID2) a2 = fmaf(w, Cr[d2], a2);
    }
    atomicAdd(&q2c[d0], a0*inv);
    if (d1 < HID2) atomicAdd(&q2c[d1], a1*inv);
    if (d2 < HID2) atomicAdd(&q2c[d2], a2*inv);
}

__global__ void qac_kernel(const float* __restrict__ C, const float* __restrict__ c2q,
                           const float* __restrict__ q2c, float* __restrict__ qac)
{
    size_t i = (size_t)blockIdx.x*256 + threadIdx.x;
    if (i >= (size_t)SEQ_C*HID2) return;
    size_t c = i / HID2, d = i % HID2;
    float cv = C[i], aq = c2q[i];
    float* row = qac + c*QACD;
    row[d] = cv;
    row[HID2 + d] = aq;
    row[2*HID2 + d] = cv*aq;
    row[3*HID2 + d] = cv*q2c[d];
}

__global__ void poslogit(const float* __restrict__ qac, const float* __restrict__ M,
                         const float* __restrict__ w, float* __restrict__ lo)
{
    int c = blockIdx.x, t = threadIdx.x;
    float acc = 0.f;
    const float* qr = qac + (size_t)c*QACD;
    for (int j = t; j < QACD; j += 128) acc = fmaf(qr[j], w[j], acc);
    const float* mr = M + (size_t)c*HID2;
    for (int j = t; j < HID2; j += 128) acc = fmaf(mr[j], w[QACD + j], acc);
    __shared__ float red[4];
    for (int o = 16; o; o >>= 1) acc += __shfl_xor_sync(~0u, acc, o);
    if ((t & 31) == 0) red[t >> 5] = acc;
    __syncthreads();
    if (t == 0) lo[c] = red[0] + red[1] + red[2] + red[3];
}

__global__ void final_softmax(const float* __restrict__ lo, float* __restrict__ out)
{
    int t = threadIdx.x;
    __shared__ float red[32];
    __shared__ float sh[2];
    for (int v = 0; v < 2; v++) {
        const float* l = lo + v*SEQ_C;
        float m = -1e30f;
        for (int i = t; i < SEQ_C; i += 1024) m = fmaxf(m, l[i]);
        for (int o = 16; o; o >>= 1) m = fmaxf(m, __shfl_xor_sync(~0u, m, o));
        if ((t & 31) == 0) red[t >> 5] = m;
        __syncthreads();
        if (t < 32) {
            float w = red[t];
            for (int o = 16; o; o >>= 1) w = fmaxf(w, __shfl_xor_sync(~0u, w, o));
            if (t == 0) sh[0] = w;
        }
        __syncthreads();
        float gm = sh[0];
        float e = 0.f;
        for (int i = t; i < SEQ_C; i += 1024) e += __expf(l[i] - gm);
        for (int o = 16; o; o >>= 1) e += __shfl_xor_sync(~0u, e, o);
        if ((t & 31) == 0) red[t >> 5] = e;
        __syncthreads();
        if (t < 32) {
            float w = red[t];
            for (int o = 16; o; o >>= 1) w += __shfl_xor_sync(~0u, w, o);
            if (t == 0) sh[1] = w;
        }
        __syncthreads();
        float inv = 1.f/sh[1];
        for (int i = t; i < SEQ_C; i += 1024) out[v*SEQ_C + i] = __expf(l[i] - gm)*inv;
        __syncthreads();
    }
}

// ---------------- host orchestration ----------------
static inline void gemm(const float* A, const float* B, const float* bias, float* C,
                        int M, int N, int K)
{
    dim3 g((N + 63)/64, (M + 63)/64);
    gemm_abT<<<g, 256>>>(A, B, bias, C, M, N, K);
}

// one launch: seg0 (T0 steps) always; seg1 (T1 steps) iff T1 > 0
static void launch_lstm2(const float* xwf0, const float* xwb0,
                         const float* xwf1, const float* xwb1,
                         const float* whh, const float* h00, const float* h01,
                         float* out0, float* out1, int T0, int T1,
                         float* zb, unsigned* ctr, int ctri)
{
    int nclu = (T1 > 0) ? 4 : 2;
    cudaLaunchConfig_t cfg = {};
    cfg.gridDim = dim3(16*nclu, 1, 1);
    cfg.blockDim = dim3(384, 1, 1);
    cfg.dynamicSmemBytes = 0;
    cfg.stream = 0;
    cudaLaunchAttribute a[1];
    a[0].id = cudaLaunchAttributeClusterDimension;
    a[0].val.clusterDim.x = 16; a[0].val.clusterDim.y = 1; a[0].val.clusterDim.z = 1;
    cfg.attrs = a; cfg.numAttrs = 1;
    cudaError_t e = cudaLaunchKernelEx(&cfg, lstm_cluster, xwf0, xwb0, xwf1, xwb1,
                                       whh, h00, h01, out0, out1, T0, T1);
    if (e != cudaSuccess) {
        (void)cudaGetLastError();
        lstm_stage<<<32, 384>>>(xwf0, xwb0, whh, h00, out0, zb, ctr + ctri, T0);
        if (T1 > 0)
            lstm_stage<<<32, 384>>>(xwf1, xwb1, whh, h01, out1, zb, ctr + ctri + 1, T1);
    }
}

extern "C" void kernel_launch(void* const* d_in, const int* in_sizes, int n_in,
                              void* d_out, int out_size)
{
    (void)in_sizes; (void)n_in; (void)out_size;
    float* S = nullptr; unsigned* CT = nullptr;
    cudaGetSymbolAddress((void**)&S, g_s);
    cudaGetSymbolAddress((void**)&CT, g_ctr);
    cudaFuncSetAttribute(lstm_cluster, cudaFuncAttributeNonPortableClusterSizeAllowed, 1);

    const int*   chars_ctx = (const int*)d_in[0];
    const int*   chars_qry = (const int*)d_in[1];
    const float* elmo_ctx  = (const float*)d_in[2];
    const float* elmo_qry  = (const float*)d_in[3];
    const float* char_emb  = (const float*)d_in[4];
    const float* conv_w    = (const float*)d_in[5];
    const float* conv_b    = (const float*)d_in[6];
    const float* hw_pw     = (const float*)d_in[7];
    const float* hw_pb     = (const float*)d_in[8];
    const float* hw_gw     = (const float*)d_in[9];
    const float* hw_gb     = (const float*)d_in[10];
    const float* ctx_Wih   = (const float*)d_in[11];
    const float* ctx_Whh   = (const float*)d_in[12];
    const float* ctx_b     = (const float*)d_in[13];
    const float* sim_w     = (const float*)d_in[14];
    const float* m1_Wih    = (const float*)d_in[15];
    const float* m1_Whh    = (const float*)d_in[16];
    const float* m1_b      = (const float*)d_in[17];
    const float* m2_Wih    = (const float*)d_in[18];
    const float* m2_Whh    = (const float*)d_in[19];
    const float* m2_b      = (const float*)d_in[20];
    const float* po_Wih    = (const float*)d_in[21];
    const float* po_Whh    = (const float*)d_in[22];
    const float* po_b      = (const float*)d_in[23];
    const float* pos1_w    = (const float*)d_in[24];
    const float* pos2_w    = (const float*)d_in[25];
    const float* h0_ctx_c  = (const float*)d_in[26];
    const float* h0_ctx_q  = (const float*)d_in[27];
    const float* h0_mod    = (const float*)d_in[28];
    const float* h0_pos    = (const float*)d_in[29];

    float* X    = S + OFF_X;
    float* GL   = S + OFF_G;
    float* PL   = S + OFF_P;
    float* XWF  = S + OFF_XWF;
    float* XWB  = S + OFF_XWB;
    float* CQ   = S + OFF_CQ;
    float* C2Q  = S + OFF_C2Q;
    float* QAC  = S + OFF_QAC;
    float* M1   = S + OFF_M1;
    float* M2   = S + OFF_M2;
    float* ROWM = S + OFF_ROWM;
    float* QD   = S + OFF_QD;
    float* GST  = S + OFF_GST;
    float* Q2C  = S + OFF_Q2C;
    float* LO   = S + OFF_LO;
    float* ZB   = S + OFF_ZB;
    float* Cm   = CQ;
    float* Qm   = CQ + (size_t)SEQ_C*HID2;

    cudaMemsetAsync(CT, 0, 8*sizeof(unsigned), 0);

    // embedding
    cnn_kernel<<<NTOK, 128>>>(chars_ctx, chars_qry, char_emb, conv_w, conv_b, X);
    elmo_copy<<<(NTOK*256 + 255)/256, 256>>>(elmo_ctx, elmo_qry, X);

    // highway x2
    for (int l = 0; l < 2; l++) {
        gemm(X, hw_gw + (size_t)l*HID*HID, hw_gb + (size_t)l*HID, GL, NTOK, HID, HID);
        gemm(X, hw_pw + (size_t)l*HID*HID, hw_pb + (size_t)l*HID, PL, NTOK, HID, HID);
        hw_combine<<<(NTOK*HID + 255)/256, 256>>>(GL, PL, X, NTOK*HID);
    }

    // context BiLSTM (C tokens + Q tokens in one 4-cluster launch)
    gemm(X, ctx_Wih,                    ctx_b,      XWF, NTOK, G4, HID);
    gemm(X, ctx_Wih + (size_t)G4*HID,   ctx_b + G4, XWB, NTOK, G4, HID);
    launch_lstm2(XWF, XWB,
                 XWF + (size_t)SEQ_C*G4, XWB + (size_t)SEQ_C*G4,
                 ctx_Whh, h0_ctx_c, h0_ctx_q, Cm, Qm, SEQ_C, SEQ_Q, ZB, CT, 0);

    // attention
    qdot_kernel<<<SEQ_Q, 128>>>(Qm, sim_w, QD);
    attn_kernel<<<SEQ_C, 256>>>(Cm, Qm, sim_w, QD, C2Q, ROWM);
    q2c_prep<<<1, 1024>>>(ROWM, GST, Q2C);
    q2c_acc<<<32, 256>>>(ROWM, GST, Cm, Q2C);
    qac_kernel<<<(int)(((size_t)SEQ_C*HID2 + 255)/256), 256>>>(Cm, C2Q, Q2C, QAC);

    // modeling layer 1
    gemm(QAC, m1_Wih,                    m1_b,      XWF, SEQ_C, G4, QACD);
    gemm(QAC, m1_Wih + (size_t)G4*QACD,  m1_b + G4, XWB, SEQ_C, G4, QACD);
    launch_lstm2(XWF, XWB, XWF, XWB, m1_Whh, h0_mod, h0_mod,
                 M1, M1, SEQ_C, 0, ZB, CT, 2);

    // modeling layer 2
    gemm(M1, m2_Wih,                    m2_b,      XWF, SEQ_C, G4, HID2);
    gemm(M1, m2_Wih + (size_t)G4*HID2,  m2_b + G4, XWB, SEQ_C, G4, HID2);
    launch_lstm2(XWF, XWB, XWF, XWB, m2_Whh, h0_mod + 2*HID, h0_mod + 2*HID,
                 M2, M2, SEQ_C, 0, ZB, CT, 3);

    // pos1 logits
    poslogit<<<SEQ_C, 128>>>(QAC, M2, pos1_w, LO);

    // pos BiLSTM (reuses M1 buffer)
    gemm(M2, po_Wih,                    po_b,      XWF, SEQ_C, G4, HID2);
    gemm(M2, po_Wih + (size_t)G4*HID2,  po_b + G4, XWB, SEQ_C, G4, HID2);
    launch_lstm2(XWF, XWB, XWF, XWB, po_Whh, h0_pos, h0_pos,
                 M1, M1, SEQ_C, 0, ZB, CT, 4);

    // pos2 logits + final softmaxes
    poslogit<<<SEQ_C, 128>>>(QAC, M1, pos2_w, LO + SEQ_C);
    final_softmax<<<1, 1024>>>(LO, (float*)d_out);
}